// round 1
// baseline (speedup 1.0000x reference)
#include <cuda_runtime.h>
#include <cuda_bf16.h>
#include <math.h>

#define BATCH 1024
#define SEQ   200
#define NLIN  400
#define HID   128
#define H2    256
#define H3    384
#define TB    16
#define HPAD  132

// ---------------- scratch (static device globals; no allocation) ----------------
__device__ float g_code[(size_t)BATCH * NLIN];            // 1.6 MB
__device__ float g_h0  [(size_t)BATCH * SEQ * H2];        // 210 MB
__device__ float g_xg1 [(size_t)2 * BATCH * SEQ * H3];    // 629 MB
__device__ float g_h1  [(size_t)BATCH * SEQ * H2];        // 210 MB

__device__ __forceinline__ float sigf(float x) {
    return 1.f / (1.f + __expf(-x));
}
__device__ __forceinline__ float tanhfast(float x) {
    float e = __expf(-2.f * fabsf(x));
    float t = (1.f - e) / (1.f + e);
    return x < 0.f ? -t : t;
}

// ---------------- generic SGEMM: C[M,N] = A[M,K] * B[N,K]^T + bias[N] ----------------
// Requires M % 64 == 0, K % 16 == 0. N guarded.
__global__ __launch_bounds__(256) void sgemm_nt(
    const float* __restrict__ A, const float* __restrict__ B,
    const float* __restrict__ bias, float* __restrict__ C,
    int M, int N, int K)
{
    __shared__ float As[16][65];
    __shared__ float Bs[16][65];
    int tid = threadIdx.x;
    int tx = tid & 15, ty = tid >> 4;
    int bm0 = blockIdx.x * 64, bn0 = blockIdx.y * 64;
    int lrow = tid >> 2;            // 0..63
    int lc4  = (tid & 3) * 4;       // 0,4,8,12

    float acc[4][4] = {};

    for (int k0 = 0; k0 < K; k0 += 16) {
        float4 av = *(const float4*)(A + (size_t)(bm0 + lrow) * K + k0 + lc4);
        float4 bv = make_float4(0.f, 0.f, 0.f, 0.f);
        if (bn0 + lrow < N)
            bv = *(const float4*)(B + (size_t)(bn0 + lrow) * K + k0 + lc4);
        As[lc4 + 0][lrow] = av.x; As[lc4 + 1][lrow] = av.y;
        As[lc4 + 2][lrow] = av.z; As[lc4 + 3][lrow] = av.w;
        Bs[lc4 + 0][lrow] = bv.x; Bs[lc4 + 1][lrow] = bv.y;
        Bs[lc4 + 2][lrow] = bv.z; Bs[lc4 + 3][lrow] = bv.w;
        __syncthreads();
        #pragma unroll
        for (int kk = 0; kk < 16; ++kk) {
            float a[4], b[4];
            #pragma unroll
            for (int i = 0; i < 4; ++i) { a[i] = As[kk][ty * 4 + i]; b[i] = Bs[kk][tx * 4 + i]; }
            #pragma unroll
            for (int i = 0; i < 4; ++i)
                #pragma unroll
                for (int j = 0; j < 4; ++j)
                    acc[i][j] = fmaf(a[i], b[j], acc[i][j]);
        }
        __syncthreads();
    }

    #pragma unroll
    for (int i = 0; i < 4; ++i) {
        int row = bm0 + ty * 4 + i;
        #pragma unroll
        for (int j = 0; j < 4; ++j) {
            int col = bn0 + tx * 4 + j;
            if (col < N)
                C[(size_t)row * N + col] = acc[i][j] + bias[col];
        }
    }
}

// ---------------- persistent bidirectional GRU layer ----------------
// grid: (BATCH/TB, 2 dirs), 256 threads.
// LAYER==0: input gates computed inline from g_code via Wih (din=2).
// LAYER==1: input gates (incl. bih) precomputed in xg [2][B*L][384].
// Shared layout: Whh transposed [128][384] + h[TB][HPAD] + bih[384] + bhh[384] + Wih[384*2]
#define SMEM_GRU ((128 * 384 + TB * HPAD + 384 + 384 + 768) * sizeof(float))

template <int LAYER>
__global__ __launch_bounds__(256) void gru_kernel(
    const float* __restrict__ code,       // [B][400] (layer0)
    const float* __restrict__ xg,         // [2][B*L][384] (layer1)
    const float* __restrict__ Wih_f, const float* __restrict__ Wih_b,
    const float* __restrict__ Whh_f, const float* __restrict__ Whh_b,
    const float* __restrict__ bih_f, const float* __restrict__ bih_b,
    const float* __restrict__ bhh_f, const float* __restrict__ bhh_b,
    float* __restrict__ hout)             // [B][L][256] (fwd cols 0..127, bwd 128..255)
{
    extern __shared__ float smem[];
    float* sWt  = smem;                       // [128][384]
    float* sh   = sWt + 128 * 384;            // [TB][HPAD]
    float* sbih = sh + TB * HPAD;             // [384]
    float* sbhh = sbih + 384;                 // [384]
    float* sWih = sbhh + 384;                 // [384][2]

    const int dir = blockIdx.y;
    const float* Whh = dir ? Whh_b : Whh_f;
    const float* bhh = dir ? bhh_b : bhh_f;
    const int tid = threadIdx.x;

    // Load Whh transposed: sWt[j][g] = Whh[g][j]
    for (int idx = tid; idx < 128 * 384; idx += 256) {
        int g = idx >> 7, j = idx & 127;
        sWt[j * H3 + g] = Whh[idx];
    }
    for (int idx = tid; idx < H3; idx += 256) {
        sbhh[idx] = bhh[idx];
        if (LAYER == 0) {
            const float* Wih = dir ? Wih_b : Wih_f;
            const float* bih = dir ? bih_b : bih_f;
            sbih[idx] = bih[idx];
            sWih[idx * 2 + 0] = Wih[idx * 2 + 0];
            sWih[idx * 2 + 1] = Wih[idx * 2 + 1];
        }
    }
    for (int idx = tid; idx < TB * HPAD; idx += 256) sh[idx] = 0.f;
    __syncthreads();

    const int w = tid >> 5, l = tid & 31;
    const int k = (w & 3) * 32 + l;       // hidden index this thread owns
    const int bbase = (w >> 2) * 8;       // 8 batch rows per thread
    const int gb0 = blockIdx.x * TB;

    for (int t = 0; t < SEQ; ++t) {
        const int tt = dir ? (SEQ - 1 - t) : t;

        float a0[8], a1[8], a2[8];
        #pragma unroll
        for (int i = 0; i < 8; ++i) { a0[i] = 0.f; a1[i] = 0.f; a2[i] = 0.f; }

        // hg = h @ Whh^T : thread computes gates (r,z,n) at index k for 8 batch rows
        #pragma unroll 4
        for (int j = 0; j < HID; ++j) {
            float w0 = sWt[j * H3 + k];
            float w1 = sWt[j * H3 + 128 + k];
            float w2 = sWt[j * H3 + 256 + k];
            #pragma unroll
            for (int i = 0; i < 8; ++i) {
                float hv = sh[(bbase + i) * HPAD + j];
                a0[i] = fmaf(hv, w0, a0[i]);
                a1[i] = fmaf(hv, w1, a1[i]);
                a2[i] = fmaf(hv, w2, a2[i]);
            }
        }
        __syncthreads();   // everyone done reading sh

        const float bh0 = sbhh[k], bh1 = sbhh[128 + k], bh2 = sbhh[256 + k];
        #pragma unroll
        for (int i = 0; i < 8; ++i) {
            const int b = bbase + i;
            const int gb = gb0 + b;
            float xr, xz, xn;
            if (LAYER == 0) {
                float c0 = code[(size_t)gb * NLIN + tt * 2 + 0];
                float c1 = code[(size_t)gb * NLIN + tt * 2 + 1];
                xr = fmaf(c0, sWih[(k)       * 2], fmaf(c1, sWih[(k)       * 2 + 1], sbih[k]));
                xz = fmaf(c0, sWih[(128 + k) * 2], fmaf(c1, sWih[(128 + k) * 2 + 1], sbih[128 + k]));
                xn = fmaf(c0, sWih[(256 + k) * 2], fmaf(c1, sWih[(256 + k) * 2 + 1], sbih[256 + k]));
            } else {
                size_t base = ((size_t)dir * BATCH * SEQ + (size_t)gb * SEQ + tt) * H3;
                xr = xg[base + k];
                xz = xg[base + 128 + k];
                xn = xg[base + 256 + k];
            }
            float r = sigf(xr + a0[i] + bh0);
            float z = sigf(xz + a1[i] + bh1);
            float n = tanhfast(xn + r * (a2[i] + bh2));
            float hp = sh[b * HPAD + k];
            float hn = (1.f - z) * n + z * hp;
            sh[b * HPAD + k] = hn;
            hout[((size_t)gb * SEQ + tt) * H2 + dir * HID + k] = hn;
        }
        __syncthreads();   // sh updated before next step's matmul
    }
}

// ---------------- final head: out = sigmoid(h1 . Wf + bf) ----------------
__global__ __launch_bounds__(256) void final_kernel(
    const float* __restrict__ h1, const float* __restrict__ Wf,
    const float* __restrict__ bf, float* __restrict__ out)
{
    __shared__ float sW[H2];
    int tid = threadIdx.x;
    sW[tid] = Wf[tid];
    __syncthreads();
    int w = tid >> 5, l = tid & 31;
    size_t row = (size_t)blockIdx.x * 8 + w;
    const float* hr = h1 + row * H2;
    float s = 0.f;
    #pragma unroll
    for (int i = 0; i < 8; ++i)
        s = fmaf(hr[l + i * 32], sW[l + i * 32], s);
    #pragma unroll
    for (int off = 16; off; off >>= 1)
        s += __shfl_xor_sync(0xffffffffu, s, off);
    if (l == 0)
        out[row] = 1.f / (1.f + __expf(-(s + bf[0])));
}

// ---------------- launch ----------------
extern "C" void kernel_launch(void* const* d_in, const int* in_sizes, int n_in,
                              void* d_out, int out_size)
{
    const float* received = (const float*)d_in[0];
    const float* W_lin    = (const float*)d_in[1];
    const float* b_lin    = (const float*)d_in[2];
    const float* Wih0f = (const float*)d_in[3],  *Whh0f = (const float*)d_in[4];
    const float* bih0f = (const float*)d_in[5],  *bhh0f = (const float*)d_in[6];
    const float* Wih0b = (const float*)d_in[7],  *Whh0b = (const float*)d_in[8];
    const float* bih0b = (const float*)d_in[9],  *bhh0b = (const float*)d_in[10];
    const float* Wih1f = (const float*)d_in[11], *Whh1f = (const float*)d_in[12];
    const float* bih1f = (const float*)d_in[13], *bhh1f = (const float*)d_in[14];
    const float* Wih1b = (const float*)d_in[15], *Whh1b = (const float*)d_in[16];
    const float* bih1b = (const float*)d_in[17], *bhh1b = (const float*)d_in[18];
    const float* Wf    = (const float*)d_in[19], *bf    = (const float*)d_in[20];
    float* out = (float*)d_out;

    float *code, *h0, *xg1, *h1;
    cudaGetSymbolAddress((void**)&code, g_code);
    cudaGetSymbolAddress((void**)&h0,   g_h0);
    cudaGetSymbolAddress((void**)&xg1,  g_xg1);
    cudaGetSymbolAddress((void**)&h1,   g_h1);

    cudaFuncSetAttribute(gru_kernel<0>, cudaFuncAttributeMaxDynamicSharedMemorySize, (int)SMEM_GRU);
    cudaFuncSetAttribute(gru_kernel<1>, cudaFuncAttributeMaxDynamicSharedMemorySize, (int)SMEM_GRU);

    // 1) dec_linear: code[B,400] = received[B,400] @ W_lin^T + b_lin
    sgemm_nt<<<dim3(BATCH / 64, (NLIN + 63) / 64), 256>>>(
        received, W_lin, b_lin, code, BATCH, NLIN, NLIN);

    // 2) layer-0 bidirectional GRU (input gates inline, din=2)
    gru_kernel<0><<<dim3(BATCH / TB, 2), 256, SMEM_GRU>>>(
        code, nullptr, Wih0f, Wih0b, Whh0f, Whh0b, bih0f, bih0b, bhh0f, bhh0b, h0);

    // 3) layer-1 input projections: xg1[dir] = h0 @ Wih1^T + bih1
    sgemm_nt<<<dim3(BATCH * SEQ / 64, H3 / 64), 256>>>(
        h0, Wih1f, bih1f, xg1, BATCH * SEQ, H3, H2);
    sgemm_nt<<<dim3(BATCH * SEQ / 64, H3 / 64), 256>>>(
        h0, Wih1b, bih1b, xg1 + (size_t)BATCH * SEQ * H3, BATCH * SEQ, H3, H2);

    // 4) layer-1 bidirectional GRU
    gru_kernel<1><<<dim3(BATCH / TB, 2), 256, SMEM_GRU>>>(
        nullptr, xg1, nullptr, nullptr, Whh1f, Whh1b, bih1f, bih1b, bhh1f, bhh1b, h1);

    // 5) output head
    final_kernel<<<BATCH * SEQ / 8, 256>>>(h1, Wf, bf, out);
}

// round 2
// speedup vs baseline: 1.0034x; 1.0034x over previous
#include <cuda_runtime.h>
#include <cuda_bf16.h>
#include <math.h>

#define BATCH 1024
#define SEQ   200
#define NLIN  400
#define HID   128
#define H2    256
#define H3    384
#define TB    16
#define HPAD  132

// ---------------- scratch (static device globals; no allocation) ----------------
__device__ float g_code[(size_t)BATCH * NLIN];            // 1.6 MB
__device__ float g_h0  [(size_t)BATCH * SEQ * H2];        // 210 MB
__device__ float g_xg1 [(size_t)2 * BATCH * SEQ * H3];    // 629 MB
__device__ float g_h1  [(size_t)BATCH * SEQ * H2];        // 210 MB

__device__ __forceinline__ float sigf(float x) {
    return 1.f / (1.f + __expf(-x));
}
__device__ __forceinline__ float tanhfast(float x) {
    float e = __expf(-2.f * fabsf(x));
    float t = (1.f - e) / (1.f + e);
    return x < 0.f ? -t : t;
}

// ---------------- generic SGEMM: C[M,N] = A[M,K] * B[N,K]^T + bias[N] ----------------
// Requires M % 64 == 0, K % 16 == 0. N guarded.
__global__ __launch_bounds__(256) void sgemm_nt(
    const float* __restrict__ A, const float* __restrict__ B,
    const float* __restrict__ bias, float* __restrict__ C,
    int M, int N, int K)
{
    __shared__ float As[16][65];
    __shared__ float Bs[16][65];
    int tid = threadIdx.x;
    int tx = tid & 15, ty = tid >> 4;
    int bm0 = blockIdx.x * 64, bn0 = blockIdx.y * 64;
    int lrow = tid >> 2;            // 0..63
    int lc4  = (tid & 3) * 4;       // 0,4,8,12

    float acc[4][4] = {};

    for (int k0 = 0; k0 < K; k0 += 16) {
        float4 av = *(const float4*)(A + (size_t)(bm0 + lrow) * K + k0 + lc4);
        float4 bv = make_float4(0.f, 0.f, 0.f, 0.f);
        if (bn0 + lrow < N)
            bv = *(const float4*)(B + (size_t)(bn0 + lrow) * K + k0 + lc4);
        As[lc4 + 0][lrow] = av.x; As[lc4 + 1][lrow] = av.y;
        As[lc4 + 2][lrow] = av.z; As[lc4 + 3][lrow] = av.w;
        Bs[lc4 + 0][lrow] = bv.x; Bs[lc4 + 1][lrow] = bv.y;
        Bs[lc4 + 2][lrow] = bv.z; Bs[lc4 + 3][lrow] = bv.w;
        __syncthreads();
        #pragma unroll
        for (int kk = 0; kk < 16; ++kk) {
            float a[4], b[4];
            #pragma unroll
            for (int i = 0; i < 4; ++i) { a[i] = As[kk][ty * 4 + i]; b[i] = Bs[kk][tx * 4 + i]; }
            #pragma unroll
            for (int i = 0; i < 4; ++i)
                #pragma unroll
                for (int j = 0; j < 4; ++j)
                    acc[i][j] = fmaf(a[i], b[j], acc[i][j]);
        }
        __syncthreads();
    }

    #pragma unroll
    for (int i = 0; i < 4; ++i) {
        int row = bm0 + ty * 4 + i;
        #pragma unroll
        for (int j = 0; j < 4; ++j) {
            int col = bn0 + tx * 4 + j;
            if (col < N)
                C[(size_t)row * N + col] = acc[i][j] + bias[col];
        }
    }
}

// ---------------- persistent bidirectional GRU layer ----------------
// grid: (BATCH/TB, 2 dirs), 256 threads.
// LAYER==0: input gates computed inline from g_code via Wih (din=2).
// LAYER==1: input gates (incl. bih) precomputed in xg [2][B*L][384].
// Shared layout: Whh transposed [128][384] + h[TB][HPAD] + bih[384] + bhh[384] + Wih[384*2]
#define SMEM_GRU ((128 * 384 + TB * HPAD + 384 + 384 + 768) * sizeof(float))

template <int LAYER>
__global__ __launch_bounds__(256) void gru_kernel(
    const float* __restrict__ code,       // [B][400] (layer0)
    const float* __restrict__ xg,         // [2][B*L][384] (layer1)
    const float* __restrict__ Wih_f, const float* __restrict__ Wih_b,
    const float* __restrict__ Whh_f, const float* __restrict__ Whh_b,
    const float* __restrict__ bih_f, const float* __restrict__ bih_b,
    const float* __restrict__ bhh_f, const float* __restrict__ bhh_b,
    float* __restrict__ hout)             // [B][L][256] (fwd cols 0..127, bwd 128..255)
{
    extern __shared__ float smem[];
    float* sWt  = smem;                       // [128][384]
    float* sh   = sWt + 128 * 384;            // [TB][HPAD]
    float* sbih = sh + TB * HPAD;             // [384]
    float* sbhh = sbih + 384;                 // [384]
    float* sWih = sbhh + 384;                 // [384][2]

    const int dir = blockIdx.y;
    const float* Whh = dir ? Whh_b : Whh_f;
    const float* bhh = dir ? bhh_b : bhh_f;
    const int tid = threadIdx.x;

    // Load Whh transposed: sWt[j][g] = Whh[g][j]
    for (int idx = tid; idx < 128 * 384; idx += 256) {
        int g = idx >> 7, j = idx & 127;
        sWt[j * H3 + g] = Whh[idx];
    }
    for (int idx = tid; idx < H3; idx += 256) {
        sbhh[idx] = bhh[idx];
        if (LAYER == 0) {
            const float* Wih = dir ? Wih_b : Wih_f;
            const float* bih = dir ? bih_b : bih_f;
            sbih[idx] = bih[idx];
            sWih[idx * 2 + 0] = Wih[idx * 2 + 0];
            sWih[idx * 2 + 1] = Wih[idx * 2 + 1];
        }
    }
    for (int idx = tid; idx < TB * HPAD; idx += 256) sh[idx] = 0.f;
    __syncthreads();

    const int w = tid >> 5, l = tid & 31;
    const int k = (w & 3) * 32 + l;       // hidden index this thread owns
    const int bbase = (w >> 2) * 8;       // 8 batch rows per thread
    const int gb0 = blockIdx.x * TB;

    for (int t = 0; t < SEQ; ++t) {
        const int tt = dir ? (SEQ - 1 - t) : t;

        float a0[8], a1[8], a2[8];
        #pragma unroll
        for (int i = 0; i < 8; ++i) { a0[i] = 0.f; a1[i] = 0.f; a2[i] = 0.f; }

        // hg = h @ Whh^T : thread computes gates (r,z,n) at index k for 8 batch rows
        #pragma unroll 4
        for (int j = 0; j < HID; ++j) {
            float w0 = sWt[j * H3 + k];
            float w1 = sWt[j * H3 + 128 + k];
            float w2 = sWt[j * H3 + 256 + k];
            #pragma unroll
            for (int i = 0; i < 8; ++i) {
                float hv = sh[(bbase + i) * HPAD + j];
                a0[i] = fmaf(hv, w0, a0[i]);
                a1[i] = fmaf(hv, w1, a1[i]);
                a2[i] = fmaf(hv, w2, a2[i]);
            }
        }
        __syncthreads();   // everyone done reading sh

        const float bh0 = sbhh[k], bh1 = sbhh[128 + k], bh2 = sbhh[256 + k];
        #pragma unroll
        for (int i = 0; i < 8; ++i) {
            const int b = bbase + i;
            const int gb = gb0 + b;
            float xr, xz, xn;
            if (LAYER == 0) {
                float c0 = code[(size_t)gb * NLIN + tt * 2 + 0];
                float c1 = code[(size_t)gb * NLIN + tt * 2 + 1];
                xr = fmaf(c0, sWih[(k)       * 2], fmaf(c1, sWih[(k)       * 2 + 1], sbih[k]));
                xz = fmaf(c0, sWih[(128 + k) * 2], fmaf(c1, sWih[(128 + k) * 2 + 1], sbih[128 + k]));
                xn = fmaf(c0, sWih[(256 + k) * 2], fmaf(c1, sWih[(256 + k) * 2 + 1], sbih[256 + k]));
            } else {
                size_t base = ((size_t)dir * BATCH * SEQ + (size_t)gb * SEQ + tt) * H3;
                xr = xg[base + k];
                xz = xg[base + 128 + k];
                xn = xg[base + 256 + k];
            }
            float r = sigf(xr + a0[i] + bh0);
            float z = sigf(xz + a1[i] + bh1);
            float n = tanhfast(xn + r * (a2[i] + bh2));
            float hp = sh[b * HPAD + k];
            float hn = (1.f - z) * n + z * hp;
            sh[b * HPAD + k] = hn;
            hout[((size_t)gb * SEQ + tt) * H2 + dir * HID + k] = hn;
        }
        __syncthreads();   // sh updated before next step's matmul
    }
}

// ---------------- final head: out = sigmoid(h1 . Wf + bf) ----------------
__global__ __launch_bounds__(256) void final_kernel(
    const float* __restrict__ h1, const float* __restrict__ Wf,
    const float* __restrict__ bf, float* __restrict__ out)
{
    __shared__ float sW[H2];
    int tid = threadIdx.x;
    sW[tid] = Wf[tid];
    __syncthreads();
    int w = tid >> 5, l = tid & 31;
    size_t row = (size_t)blockIdx.x * 8 + w;
    const float* hr = h1 + row * H2;
    float s = 0.f;
    #pragma unroll
    for (int i = 0; i < 8; ++i)
        s = fmaf(hr[l + i * 32], sW[l + i * 32], s);
    #pragma unroll
    for (int off = 16; off; off >>= 1)
        s += __shfl_xor_sync(0xffffffffu, s, off);
    if (l == 0)
        out[row] = 1.f / (1.f + __expf(-(s + bf[0])));
}

// ---------------- launch ----------------
extern "C" void kernel_launch(void* const* d_in, const int* in_sizes, int n_in,
                              void* d_out, int out_size)
{
    const float* received = (const float*)d_in[0];
    const float* W_lin    = (const float*)d_in[1];
    const float* b_lin    = (const float*)d_in[2];
    const float* Wih0f = (const float*)d_in[3],  *Whh0f = (const float*)d_in[4];
    const float* bih0f = (const float*)d_in[5],  *bhh0f = (const float*)d_in[6];
    const float* Wih0b = (const float*)d_in[7],  *Whh0b = (const float*)d_in[8];
    const float* bih0b = (const float*)d_in[9],  *bhh0b = (const float*)d_in[10];
    const float* Wih1f = (const float*)d_in[11], *Whh1f = (const float*)d_in[12];
    const float* bih1f = (const float*)d_in[13], *bhh1f = (const float*)d_in[14];
    const float* Wih1b = (const float*)d_in[15], *Whh1b = (const float*)d_in[16];
    const float* bih1b = (const float*)d_in[17], *bhh1b = (const float*)d_in[18];
    const float* Wf    = (const float*)d_in[19], *bf    = (const float*)d_in[20];
    float* out = (float*)d_out;

    float *code, *h0, *xg1, *h1;
    cudaGetSymbolAddress((void**)&code, g_code);
    cudaGetSymbolAddress((void**)&h0,   g_h0);
    cudaGetSymbolAddress((void**)&xg1,  g_xg1);
    cudaGetSymbolAddress((void**)&h1,   g_h1);

    cudaFuncSetAttribute(gru_kernel<0>, cudaFuncAttributeMaxDynamicSharedMemorySize, (int)SMEM_GRU);
    cudaFuncSetAttribute(gru_kernel<1>, cudaFuncAttributeMaxDynamicSharedMemorySize, (int)SMEM_GRU);

    // 1) dec_linear: code[B,400] = received[B,400] @ W_lin^T + b_lin
    sgemm_nt<<<dim3(BATCH / 64, (NLIN + 63) / 64), 256>>>(
        received, W_lin, b_lin, code, BATCH, NLIN, NLIN);

    // 2) layer-0 bidirectional GRU (input gates inline, din=2)
    gru_kernel<0><<<dim3(BATCH / TB, 2), 256, SMEM_GRU>>>(
        code, nullptr, Wih0f, Wih0b, Whh0f, Whh0b, bih0f, bih0b, bhh0f, bhh0b, h0);

    // 3) layer-1 input projections: xg1[dir] = h0 @ Wih1^T + bih1
    sgemm_nt<<<dim3(BATCH * SEQ / 64, H3 / 64), 256>>>(
        h0, Wih1f, bih1f, xg1, BATCH * SEQ, H3, H2);
    sgemm_nt<<<dim3(BATCH * SEQ / 64, H3 / 64), 256>>>(
        h0, Wih1b, bih1b, xg1 + (size_t)BATCH * SEQ * H3, BATCH * SEQ, H3, H2);

    // 4) layer-1 bidirectional GRU
    gru_kernel<1><<<dim3(BATCH / TB, 2), 256, SMEM_GRU>>>(
        nullptr, xg1, nullptr, nullptr, Whh1f, Whh1b, bih1f, bih1b, bhh1f, bhh1b, h1);

    // 5) output head
    final_kernel<<<BATCH * SEQ / 8, 256>>>(h1, Wf, bf, out);
}

// round 3
// speedup vs baseline: 1.2942x; 1.2899x over previous
#include <cuda_runtime.h>
#include <cuda_bf16.h>
#include <math.h>

#define BATCH 1024
#define SEQ   200
#define NLIN  400
#define HID   128
#define H2    256
#define H3    384
#define TB    16
#define BL    (BATCH * SEQ)

typedef unsigned long long ull;

// ---------------- scratch (static device globals; no allocation) ----------------
__device__ float g_code[(size_t)BATCH * NLIN];            // 1.6 MB
__device__ float g_h0  [(size_t)BL * H2];                 // 210 MB
__device__ float g_xg1 [(size_t)2 * BL * H3];             // 629 MB
__device__ float g_h1  [(size_t)BL * H2];                 // 210 MB

__device__ __forceinline__ float sigf(float x) {
    return 1.f / (1.f + __expf(-x));
}
__device__ __forceinline__ float tanhfast(float x) {
    float e = __expf(-2.f * fabsf(x));
    float t = (1.f - e) / (1.f + e);
    return x < 0.f ? -t : t;
}

// ---- packed f32x2 helpers (FFMA2 path, sm_100+) ----
__device__ __forceinline__ ull pk2(float lo, float hi) {
    ull r; asm("mov.b64 %0, {%1, %2};" : "=l"(r) : "f"(lo), "f"(hi)); return r;
}
__device__ __forceinline__ ull dup2(float x) {
    ull r; asm("mov.b64 %0, {%1, %1};" : "=l"(r) : "f"(x)); return r;
}
__device__ __forceinline__ void ffma2(ull& d, ull a, ull b) {
    asm("fma.rn.f32x2 %0, %1, %2, %0;" : "+l"(d) : "l"(a), "l"(b));
}
__device__ __forceinline__ float2 unpk2(ull v) {
    float2 r; asm("mov.b64 {%0, %1}, %2;" : "=f"(r.x), "=f"(r.y) : "l"(v)); return r;
}

// ---------------- small SGEMM for dec_linear: C[M,N] = A[M,K]*B[N,K]^T + bias ----------------
__global__ __launch_bounds__(256) void sgemm_nt(
    const float* __restrict__ A, const float* __restrict__ B,
    const float* __restrict__ bias, float* __restrict__ C,
    int M, int N, int K)
{
    __shared__ float As[16][65];
    __shared__ float Bs[16][65];
    int tid = threadIdx.x;
    int tx = tid & 15, ty = tid >> 4;
    int bm0 = blockIdx.x * 64, bn0 = blockIdx.y * 64;
    int lrow = tid >> 2;
    int lc4  = (tid & 3) * 4;

    float acc[4][4] = {};

    for (int k0 = 0; k0 < K; k0 += 16) {
        float4 av = *(const float4*)(A + (size_t)(bm0 + lrow) * K + k0 + lc4);
        float4 bv = make_float4(0.f, 0.f, 0.f, 0.f);
        if (bn0 + lrow < N)
            bv = *(const float4*)(B + (size_t)(bn0 + lrow) * K + k0 + lc4);
        As[lc4 + 0][lrow] = av.x; As[lc4 + 1][lrow] = av.y;
        As[lc4 + 2][lrow] = av.z; As[lc4 + 3][lrow] = av.w;
        Bs[lc4 + 0][lrow] = bv.x; Bs[lc4 + 1][lrow] = bv.y;
        Bs[lc4 + 2][lrow] = bv.z; Bs[lc4 + 3][lrow] = bv.w;
        __syncthreads();
        #pragma unroll
        for (int kk = 0; kk < 16; ++kk) {
            float a[4], b[4];
            #pragma unroll
            for (int i = 0; i < 4; ++i) { a[i] = As[kk][ty * 4 + i]; b[i] = Bs[kk][tx * 4 + i]; }
            #pragma unroll
            for (int i = 0; i < 4; ++i)
                #pragma unroll
                for (int j = 0; j < 4; ++j)
                    acc[i][j] = fmaf(a[i], b[j], acc[i][j]);
        }
        __syncthreads();
    }

    #pragma unroll
    for (int i = 0; i < 4; ++i) {
        int row = bm0 + ty * 4 + i;
        #pragma unroll
        for (int j = 0; j < 4; ++j) {
            int col = bn0 + tx * 4 + j;
            if (col < N)
                C[(size_t)row * N + col] = acc[i][j] + bias[col];
        }
    }
}

// ---------------- fused layer-1 projection GEMM (both directions), FFMA2 ----------------
// C (=g_xg1) layout [2][BL][384]. A = h0 [BL][256]. Bf/Bb = Wih1 [384][256].
// Grid: (12 col-tiles, 1600 row-tiles). CTA tile 128(M) x 64(N), thread tile 8x4.
__global__ __launch_bounds__(256) void xgemm(
    const float* __restrict__ A,
    const float* __restrict__ Bf, const float* __restrict__ Bb,
    const float* __restrict__ biasf, const float* __restrict__ biasb,
    float* __restrict__ C)
{
    __shared__ float As[8][128];
    __shared__ float Bs[8][64];

    const int tid  = threadIdx.x;
    const int colt = blockIdx.x;                 // 0..11
    const size_t row0 = (size_t)blockIdx.y * 128;
    const int dir  = (colt >= 6);
    const float* B = dir ? Bb : Bf;
    const float* bias = dir ? biasb : biasf;
    const int ncol0 = (colt - 6 * dir) * 64;

    const int am = tid & 127, ak4 = (tid >> 7) * 4;
    const int bn = tid & 63,  bk2 = (tid >> 6) * 2;
    const int tx = tid & 15,  ty  = tid >> 4;
    const int m0 = ty * 8,    n0  = tx * 4;

    ull acc[8][2];
    #pragma unroll
    for (int i = 0; i < 8; ++i) { acc[i][0] = 0ULL; acc[i][1] = 0ULL; }

    const float* Arow = A + (row0 + am) * H2;
    const float* Brow = B + (size_t)(ncol0 + bn) * H2;

    for (int k0 = 0; k0 < H2; k0 += 8) {
        float4 av = *(const float4*)(Arow + k0 + ak4);
        float2 bv = *(const float2*)(Brow + k0 + bk2);
        __syncthreads();
        As[ak4 + 0][am] = av.x; As[ak4 + 1][am] = av.y;
        As[ak4 + 2][am] = av.z; As[ak4 + 3][am] = av.w;
        Bs[bk2][bn] = bv.x; Bs[bk2 + 1][bn] = bv.y;
        __syncthreads();
        #pragma unroll
        for (int kk = 0; kk < 8; ++kk) {
            const ull* bp = (const ull*)&Bs[kk][n0];
            ull b01 = bp[0], b23 = bp[1];
            float4 a03 = *(const float4*)&As[kk][m0];
            float4 a47 = *(const float4*)&As[kk][m0 + 4];
            ull d;
            d = dup2(a03.x); ffma2(acc[0][0], d, b01); ffma2(acc[0][1], d, b23);
            d = dup2(a03.y); ffma2(acc[1][0], d, b01); ffma2(acc[1][1], d, b23);
            d = dup2(a03.z); ffma2(acc[2][0], d, b01); ffma2(acc[2][1], d, b23);
            d = dup2(a03.w); ffma2(acc[3][0], d, b01); ffma2(acc[3][1], d, b23);
            d = dup2(a47.x); ffma2(acc[4][0], d, b01); ffma2(acc[4][1], d, b23);
            d = dup2(a47.y); ffma2(acc[5][0], d, b01); ffma2(acc[5][1], d, b23);
            d = dup2(a47.z); ffma2(acc[6][0], d, b01); ffma2(acc[6][1], d, b23);
            d = dup2(a47.w); ffma2(acc[7][0], d, b01); ffma2(acc[7][1], d, b23);
        }
    }

    float b0 = bias[ncol0 + n0 + 0], b1 = bias[ncol0 + n0 + 1];
    float b2 = bias[ncol0 + n0 + 2], b3 = bias[ncol0 + n0 + 3];
    float* Cb = C + (size_t)dir * BL * H3;
    #pragma unroll
    for (int i = 0; i < 8; ++i) {
        float2 v0 = unpk2(acc[i][0]);
        float2 v1 = unpk2(acc[i][1]);
        float* cp = Cb + (row0 + m0 + i) * H3 + ncol0 + n0;
        float2 o0; o0.x = v0.x + b0; o0.y = v0.y + b1;
        float2 o1; o1.x = v1.x + b2; o1.y = v1.y + b3;
        *(float2*)(cp)     = o0;
        *(float2*)(cp + 2) = o1;
    }
}

// ---------------- persistent bidirectional GRU layer (FFMA2 recurrence) ----------------
// grid: (BATCH/TB, 2 dirs), 256 threads, 1 CTA/SM.
// smem: sWt[j][384] (Whh transposed, 192KB) + shT[j][TB] (h state transposed, 8KB)
#define SMEM_GRU ((128 * H3 + 128 * TB) * sizeof(float))

template <int LAYER>
__global__ __launch_bounds__(256, 1) void gru_kernel(
    const float* __restrict__ code,       // [B][400] (layer0)
    const float* __restrict__ xg,         // [2][BL][384] (layer1)
    const float* __restrict__ Wih_f, const float* __restrict__ Wih_b,
    const float* __restrict__ Whh_f, const float* __restrict__ Whh_b,
    const float* __restrict__ bih_f, const float* __restrict__ bih_b,
    const float* __restrict__ bhh_f, const float* __restrict__ bhh_b,
    float* __restrict__ hout)             // [B][L][256]
{
    extern __shared__ float smem[];
    float* sWt = smem;                    // [128][384]: sWt[j][g] = Whh[g][j]
    float* shT = sWt + 128 * H3;          // [128][TB]:  shT[j][b]

    const int dir = blockIdx.y;
    const float* Whh = dir ? Whh_b : Whh_f;
    const float* bhh = dir ? bhh_b : bhh_f;
    const int tid = threadIdx.x;

    for (int idx = tid; idx < 128 * H3; idx += 256) {
        int g = idx >> 7, j = idx & 127;
        sWt[j * H3 + g] = Whh[idx];
    }
    for (int idx = tid; idx < 128 * TB; idx += 256) shT[idx] = 0.f;

    const int w = tid >> 5, l = tid & 31;
    const int k = (w & 3) * 32 + l;       // hidden index owned by this thread
    const int bbase = (w >> 2) * 8;       // 8 batch rows
    const int gb0 = blockIdx.x * TB;

    const float bh0 = bhh[k], bh1 = bhh[128 + k], bh2 = bhh[256 + k];
    float wr0 = 0, wr1 = 0, wz0 = 0, wz1 = 0, wn0 = 0, wn1 = 0, br = 0, bz = 0, bn = 0;
    if (LAYER == 0) {
        const float* Wih = dir ? Wih_b : Wih_f;
        const float* bih = dir ? bih_b : bih_f;
        wr0 = Wih[k * 2];         wr1 = Wih[k * 2 + 1];
        wz0 = Wih[(128 + k) * 2]; wz1 = Wih[(128 + k) * 2 + 1];
        wn0 = Wih[(256 + k) * 2]; wn1 = Wih[(256 + k) * 2 + 1];
        br = bih[k]; bz = bih[128 + k]; bn = bih[256 + k];
    }
    __syncthreads();

    for (int t = 0; t < SEQ; ++t) {
        const int tt = dir ? (SEQ - 1 - t) : t;

        // prefetch input-gate contributions (independent of sh; overlaps matmul)
        float xr[8], xz[8], xn[8];
        #pragma unroll
        for (int i = 0; i < 8; ++i) {
            const int gb = gb0 + bbase + i;
            if (LAYER == 0) {
                float c0 = __ldg(&code[(size_t)gb * NLIN + tt * 2 + 0]);
                float c1 = __ldg(&code[(size_t)gb * NLIN + tt * 2 + 1]);
                xr[i] = fmaf(c0, wr0, fmaf(c1, wr1, br));
                xz[i] = fmaf(c0, wz0, fmaf(c1, wz1, bz));
                xn[i] = fmaf(c0, wn0, fmaf(c1, wn1, bn));
            } else {
                size_t base = ((size_t)dir * BL + (size_t)gb * SEQ + tt) * H3;
                xr[i] = __ldg(&xg[base + k]);
                xz[i] = __ldg(&xg[base + 128 + k]);
                xn[i] = __ldg(&xg[base + 256 + k]);
            }
        }

        // hg = h @ Whh^T, packed over batch pairs
        ull A0[4], A1[4], A2[4];
        #pragma unroll
        for (int p = 0; p < 4; ++p) { A0[p] = 0ULL; A1[p] = 0ULL; A2[p] = 0ULL; }

        const float* wp = sWt + k;
        const float* hbase = shT + bbase;
        #pragma unroll 2
        for (int j = 0; j < HID; ++j) {
            ull w0d = dup2(wp[j * H3]);
            ull w1d = dup2(wp[j * H3 + 128]);
            ull w2d = dup2(wp[j * H3 + 256]);
            const ull* hp = (const ull*)(hbase + j * TB);
            ull h01 = hp[0], h23 = hp[1], h45 = hp[2], h67 = hp[3];
            ffma2(A0[0], h01, w0d); ffma2(A0[1], h23, w0d);
            ffma2(A0[2], h45, w0d); ffma2(A0[3], h67, w0d);
            ffma2(A1[0], h01, w1d); ffma2(A1[1], h23, w1d);
            ffma2(A1[2], h45, w1d); ffma2(A1[3], h67, w1d);
            ffma2(A2[0], h01, w2d); ffma2(A2[1], h23, w2d);
            ffma2(A2[2], h45, w2d); ffma2(A2[3], h67, w2d);
        }
        __syncthreads();   // everyone done reading shT

        #pragma unroll
        for (int p = 0; p < 4; ++p) {
            float2 a0 = unpk2(A0[p]);
            float2 a1 = unpk2(A1[p]);
            float2 a2 = unpk2(A2[p]);
            ull* hcell = (ull*)&shT[k * TB + bbase + 2 * p];
            float2 hp2 = unpk2(*hcell);

            int i0 = 2 * p, i1 = 2 * p + 1;
            float r0 = sigf(xr[i0] + a0.x + bh0);
            float z0 = sigf(xz[i0] + a1.x + bh1);
            float n0 = tanhfast(xn[i0] + r0 * (a2.x + bh2));
            float hn0 = (1.f - z0) * n0 + z0 * hp2.x;

            float r1 = sigf(xr[i1] + a0.y + bh0);
            float z1 = sigf(xz[i1] + a1.y + bh1);
            float n1 = tanhfast(xn[i1] + r1 * (a2.y + bh2));
            float hn1 = (1.f - z1) * n1 + z1 * hp2.y;

            *hcell = pk2(hn0, hn1);

            size_t ob = ((size_t)(gb0 + bbase + i0) * SEQ + tt) * H2 + dir * HID + k;
            hout[ob] = hn0;
            hout[ob + (size_t)SEQ * H2] = hn1;
        }
        __syncthreads();   // shT updated before next step's matmul
    }
}

// ---------------- final head: out = sigmoid(h1 . Wf + bf) ----------------
__global__ __launch_bounds__(256) void final_kernel(
    const float* __restrict__ h1, const float* __restrict__ Wf,
    const float* __restrict__ bf, float* __restrict__ out)
{
    __shared__ float sW[H2];
    int tid = threadIdx.x;
    sW[tid] = Wf[tid];
    __syncthreads();
    int w = tid >> 5, l = tid & 31;
    size_t row = (size_t)blockIdx.x * 8 + w;
    const float* hr = h1 + row * H2;
    float s = 0.f;
    #pragma unroll
    for (int i = 0; i < 8; ++i)
        s = fmaf(hr[l + i * 32], sW[l + i * 32], s);
    #pragma unroll
    for (int off = 16; off; off >>= 1)
        s += __shfl_xor_sync(0xffffffffu, s, off);
    if (l == 0)
        out[row] = 1.f / (1.f + __expf(-(s + bf[0])));
}

// ---------------- launch ----------------
extern "C" void kernel_launch(void* const* d_in, const int* in_sizes, int n_in,
                              void* d_out, int out_size)
{
    const float* received = (const float*)d_in[0];
    const float* W_lin    = (const float*)d_in[1];
    const float* b_lin    = (const float*)d_in[2];
    const float* Wih0f = (const float*)d_in[3],  *Whh0f = (const float*)d_in[4];
    const float* bih0f = (const float*)d_in[5],  *bhh0f = (const float*)d_in[6];
    const float* Wih0b = (const float*)d_in[7],  *Whh0b = (const float*)d_in[8];
    const float* bih0b = (const float*)d_in[9],  *bhh0b = (const float*)d_in[10];
    const float* Wih1f = (const float*)d_in[11], *Whh1f = (const float*)d_in[12];
    const float* bih1f = (const float*)d_in[13], *bhh1f = (const float*)d_in[14];
    const float* Wih1b = (const float*)d_in[15], *Whh1b = (const float*)d_in[16];
    const float* bih1b = (const float*)d_in[17], *bhh1b = (const float*)d_in[18];
    const float* Wf    = (const float*)d_in[19], *bf    = (const float*)d_in[20];
    float* out = (float*)d_out;

    float *code, *h0, *xg1, *h1;
    cudaGetSymbolAddress((void**)&code, g_code);
    cudaGetSymbolAddress((void**)&h0,   g_h0);
    cudaGetSymbolAddress((void**)&xg1,  g_xg1);
    cudaGetSymbolAddress((void**)&h1,   g_h1);

    cudaFuncSetAttribute(gru_kernel<0>, cudaFuncAttributeMaxDynamicSharedMemorySize, (int)SMEM_GRU);
    cudaFuncSetAttribute(gru_kernel<1>, cudaFuncAttributeMaxDynamicSharedMemorySize, (int)SMEM_GRU);

    // 1) dec_linear: code[B,400] = received[B,400] @ W_lin^T + b_lin
    sgemm_nt<<<dim3(BATCH / 64, (NLIN + 63) / 64), 256>>>(
        received, W_lin, b_lin, code, BATCH, NLIN, NLIN);

    // 2) layer-0 bidirectional GRU (input gates inline, din=2)
    gru_kernel<0><<<dim3(BATCH / TB, 2), 256, SMEM_GRU>>>(
        code, nullptr, Wih0f, Wih0b, Whh0f, Whh0b, bih0f, bih0b, bhh0f, bhh0b, h0);

    // 3) fused layer-1 input projections for both directions
    xgemm<<<dim3(12, BL / 128), 256>>>(h0, Wih1f, Wih1b, bih1f, bih1b, xg1);

    // 4) layer-1 bidirectional GRU
    gru_kernel<1><<<dim3(BATCH / TB, 2), 256, SMEM_GRU>>>(
        nullptr, xg1, nullptr, nullptr, Whh1f, Whh1b, bih1f, bih1b, bhh1f, bhh1b, h1);

    // 5) output head
    final_kernel<<<BL / 8, 256>>>(h1, Wf, bf, out);
}

// round 5
// speedup vs baseline: 1.3853x; 1.0703x over previous
#include <cuda_runtime.h>
#include <cuda_bf16.h>
#include <mma.h>
#include <math.h>
#include <stdint.h>

using namespace nvcuda;

#define BATCH 1024
#define SEQ   200
#define NLIN  400
#define HID   128
#define H2    256
#define H3    384
#define TB    16
#define BL    (BATCH * SEQ)

typedef unsigned long long ull;

// ---------------- scratch (static device globals; no allocation) ----------------
__device__ float g_code[(size_t)BATCH * NLIN];                 // 1.6 MB
__device__ __nv_bfloat16 g_ah[(size_t)BL * H2];                // 105 MB (h0 hi)
__device__ __nv_bfloat16 g_al[(size_t)BL * H2];                // 105 MB (h0 lo)
__device__ float g_xg1 [(size_t)2 * BL * H3];                  // 629 MB
__device__ float g_h1  [(size_t)BL * H2];                      // 210 MB

__device__ __forceinline__ float sigf(float x) {
    return 1.f / (1.f + __expf(-x));
}
__device__ __forceinline__ float tanhfast(float x) {
    float e = __expf(-2.f * fabsf(x));
    float t = (1.f - e) / (1.f + e);
    return x < 0.f ? -t : t;
}

// ---- packed f32x2 helpers (FFMA2, plain PTX, arch-safe) ----
__device__ __forceinline__ ull pk2(float lo, float hi) {
    ull r; asm("mov.b64 %0, {%1, %2};" : "=l"(r) : "f"(lo), "f"(hi)); return r;
}
__device__ __forceinline__ ull dup2(float x) {
    ull r; asm("mov.b64 %0, {%1, %1};" : "=l"(r) : "f"(x)); return r;
}
__device__ __forceinline__ void ffma2(ull& d, ull a, ull b) {
    asm("fma.rn.f32x2 %0, %1, %2, %0;" : "+l"(d) : "l"(a), "l"(b));
}
__device__ __forceinline__ float2 unpk2(ull v) {
    float2 r; asm("mov.b64 {%0, %1}, %2;" : "=f"(r.x), "=f"(r.y) : "l"(v)); return r;
}

// ---------------- small SGEMM for dec_linear: C[M,N] = A[M,K]*B[N,K]^T + bias ----------------
__global__ __launch_bounds__(256) void sgemm_nt(
    const float* __restrict__ A, const float* __restrict__ B,
    const float* __restrict__ bias, float* __restrict__ C,
    int M, int N, int K)
{
    __shared__ float As[16][65];
    __shared__ float Bs[16][65];
    int tid = threadIdx.x;
    int tx = tid & 15, ty = tid >> 4;
    int bm0 = blockIdx.x * 64, bn0 = blockIdx.y * 64;
    int lrow = tid >> 2;
    int lc4  = (tid & 3) * 4;

    float acc[4][4] = {};

    for (int k0 = 0; k0 < K; k0 += 16) {
        float4 av = *(const float4*)(A + (size_t)(bm0 + lrow) * K + k0 + lc4);
        float4 bv = make_float4(0.f, 0.f, 0.f, 0.f);
        if (bn0 + lrow < N)
            bv = *(const float4*)(B + (size_t)(bn0 + lrow) * K + k0 + lc4);
        As[lc4 + 0][lrow] = av.x; As[lc4 + 1][lrow] = av.y;
        As[lc4 + 2][lrow] = av.z; As[lc4 + 3][lrow] = av.w;
        Bs[lc4 + 0][lrow] = bv.x; Bs[lc4 + 1][lrow] = bv.y;
        Bs[lc4 + 2][lrow] = bv.z; Bs[lc4 + 3][lrow] = bv.w;
        __syncthreads();
        #pragma unroll
        for (int kk = 0; kk < 16; ++kk) {
            float a[4], b[4];
            #pragma unroll
            for (int i = 0; i < 4; ++i) { a[i] = As[kk][ty * 4 + i]; b[i] = Bs[kk][tx * 4 + i]; }
            #pragma unroll
            for (int i = 0; i < 4; ++i)
                #pragma unroll
                for (int j = 0; j < 4; ++j)
                    acc[i][j] = fmaf(a[i], b[j], acc[i][j]);
        }
        __syncthreads();
    }

    #pragma unroll
    for (int i = 0; i < 4; ++i) {
        int row = bm0 + ty * 4 + i;
        #pragma unroll
        for (int j = 0; j < 4; ++j) {
            int col = bn0 + tx * 4 + j;
            if (col < N)
                C[(size_t)row * N + col] = acc[i][j] + bias[col];
        }
    }
}

// ---------------- tensor-core layer-1 projection via wmma bf16 (3-term hi/lo split) ----------------
// C[2][BL][384] = h0[BL][256] @ Wih1{f,b}[384][256]^T + bias.
// grid (12, BL/128): x -> (dir, 64-col tile), y -> 128-row tile. 256 threads = 8 warps (4M x 2N).
#define LDW 264
#define LDA 72
#define LDE 68
#define OFF_BIAS 0
#define OFF_WH   256
#define OFF_WL   (OFF_WH + 64 * LDW * 2)          // +33792
#define OFF_AH   (OFF_WL + 64 * LDW * 2)
#define OFF_AL   (OFF_AH + 128 * LDA * 2)
#define OFF_EPI  (OFF_AL + 128 * LDA * 2)
#define SMEM_WMMA (OFF_EPI + 128 * LDE * 4)

__global__ __launch_bounds__(256, 1) void xgemm_wmma(
    const __nv_bfloat16* __restrict__ Ah, const __nv_bfloat16* __restrict__ Al,
    const float* __restrict__ Bf, const float* __restrict__ Bb,
    const float* __restrict__ biasf, const float* __restrict__ biasb,
    float* __restrict__ C)
{
    extern __shared__ char smem[];
    float* sbias = (float*)(smem + OFF_BIAS);
    __nv_bfloat16* sWh = (__nv_bfloat16*)(smem + OFF_WH);   // [64][LDW]: sWh[n][k]
    __nv_bfloat16* sWl = (__nv_bfloat16*)(smem + OFF_WL);
    __nv_bfloat16* sAh = (__nv_bfloat16*)(smem + OFF_AH);   // [128][LDA] per 64-k chunk
    __nv_bfloat16* sAl = (__nv_bfloat16*)(smem + OFF_AL);
    float* sEpi = (float*)(smem + OFF_EPI);                 // [128][LDE]

    const int tid = threadIdx.x;
    const int wid = tid >> 5;
    const int wm = wid & 3;          // 0..3 -> rows wm*32
    const int wn = wid >> 2;         // 0..1 -> cols wn*32

    const int colt = blockIdx.x;
    const int dir  = (colt >= 6);
    const int ncol0 = (colt - 6 * dir) * 64;
    const float* W = dir ? Bb : Bf;
    const float* bias = dir ? biasb : biasf;
    float* Cb = C + (size_t)dir * BL * H3;
    const size_t m0 = (size_t)blockIdx.y * 128;

    // W tile -> bf16 hi/lo in smem (row n = output col, inner k)
    for (int idx = tid; idx < 64 * 256; idx += 256) {
        int n = idx >> 8, k = idx & 255;
        float w = W[(size_t)(ncol0 + n) * H2 + k];
        __nv_bfloat16 hi = __float2bfloat16(w);
        __nv_bfloat16 lo = __float2bfloat16(w - __bfloat162float(hi));
        sWh[n * LDW + k] = hi;
        sWl[n * LDW + k] = lo;
    }
    if (tid < 64) sbias[tid] = bias[ncol0 + tid];

    wmma::fragment<wmma::accumulator, 16, 16, 16, float> acc[2][2];
    #pragma unroll
    for (int i = 0; i < 2; ++i)
        #pragma unroll
        for (int j = 0; j < 2; ++j)
            wmma::fill_fragment(acc[i][j], 0.f);

    for (int kc = 0; kc < 4; ++kc) {
        __syncthreads();
        // load A chunk: 128 rows x 64 cols, hi + lo (uint4 = 8 bf16)
        for (int idx = tid; idx < 128 * 8; idx += 256) {
            int r = idx >> 3, c8 = (idx & 7) * 8;
            size_t g = (m0 + r) * H2 + kc * 64 + c8;
            *(uint4*)&sAh[r * LDA + c8] = *(const uint4*)&Ah[g];
            *(uint4*)&sAl[r * LDA + c8] = *(const uint4*)&Al[g];
        }
        __syncthreads();

        #pragma unroll
        for (int kk = 0; kk < 4; ++kk) {
            wmma::fragment<wmma::matrix_a, 16, 16, 16, __nv_bfloat16, wmma::row_major> fah[2], fal[2];
            wmma::fragment<wmma::matrix_b, 16, 16, 16, __nv_bfloat16, wmma::col_major> fbh[2], fbl[2];
            #pragma unroll
            for (int i = 0; i < 2; ++i) {
                const __nv_bfloat16* pa = sAh + (wm * 32 + i * 16) * LDA + kk * 16;
                const __nv_bfloat16* ql = sAl + (wm * 32 + i * 16) * LDA + kk * 16;
                wmma::load_matrix_sync(fah[i], pa, LDA);
                wmma::load_matrix_sync(fal[i], ql, LDA);
            }
            #pragma unroll
            for (int j = 0; j < 2; ++j) {
                const __nv_bfloat16* pb = sWh + (wn * 32 + j * 16) * LDW + kc * 64 + kk * 16;
                const __nv_bfloat16* pl = sWl + (wn * 32 + j * 16) * LDW + kc * 64 + kk * 16;
                wmma::load_matrix_sync(fbh[j], pb, LDW);
                wmma::load_matrix_sync(fbl[j], pl, LDW);
            }
            #pragma unroll
            for (int i = 0; i < 2; ++i)
                #pragma unroll
                for (int j = 0; j < 2; ++j) {
                    wmma::mma_sync(acc[i][j], fah[i], fbh[j], acc[i][j]);
                    wmma::mma_sync(acc[i][j], fah[i], fbl[j], acc[i][j]);
                    wmma::mma_sync(acc[i][j], fal[i], fbh[j], acc[i][j]);
                }
        }
    }

    // epilogue: fragments -> smem -> (+bias) -> global
    __syncthreads();
    #pragma unroll
    for (int i = 0; i < 2; ++i)
        #pragma unroll
        for (int j = 0; j < 2; ++j)
            wmma::store_matrix_sync(sEpi + (wm * 32 + i * 16) * LDE + wn * 32 + j * 16,
                                    acc[i][j], LDE, wmma::mem_row_major);
    __syncthreads();
    for (int idx = tid; idx < 128 * 16; idx += 256) {
        int r = idx >> 4, c4 = (idx & 15) * 4;
        float4 v = *(float4*)&sEpi[r * LDE + c4];
        v.x += sbias[c4 + 0]; v.y += sbias[c4 + 1];
        v.z += sbias[c4 + 2]; v.w += sbias[c4 + 3];
        *(float4*)(Cb + (m0 + r) * H3 + ncol0 + c4) = v;
    }
}

// ---------------- persistent bidirectional GRU layer (FFMA2, double-buffered h) ----------------
// smem: sWt[128][384] (192KB) + two h buffers [128][TB] (16KB) = 208KB
#define SMEM_GRU ((128 * H3 + 2 * 128 * TB) * sizeof(float))

template <int LAYER>
__global__ __launch_bounds__(256, 1) void gru_kernel(
    const float* __restrict__ code,       // [B][400] (layer0)
    const float* __restrict__ xg,         // [2][BL][384] (layer1)
    const float* __restrict__ Wih_f, const float* __restrict__ Wih_b,
    const float* __restrict__ Whh_f, const float* __restrict__ Whh_b,
    const float* __restrict__ bih_f, const float* __restrict__ bih_b,
    const float* __restrict__ bhh_f, const float* __restrict__ bhh_b,
    float* __restrict__ houtF,                    // layer1: [B][L][256] fp32
    __nv_bfloat16* __restrict__ houtH,            // layer0: hi
    __nv_bfloat16* __restrict__ houtL)            // layer0: lo
{
    extern __shared__ float smemf[];
    float* sWt = smemf;                   // [128][384]: sWt[j][g] = Whh[g][j]
    float* sh0 = sWt + 128 * H3;          // [128][TB]
    float* sh1 = sh0 + 128 * TB;

    const int dir = blockIdx.y;
    const float* Whh = dir ? Whh_b : Whh_f;
    const float* bhh = dir ? bhh_b : bhh_f;
    const int tid = threadIdx.x;

    for (int idx = tid; idx < 128 * H3; idx += 256) {
        int g = idx >> 7, j = idx & 127;
        sWt[j * H3 + g] = Whh[idx];
    }
    for (int idx = tid; idx < 128 * TB; idx += 256) sh0[idx] = 0.f;

    const int w = tid >> 5, l = tid & 31;
    const int k = (w & 3) * 32 + l;
    const int bbase = (w >> 2) * 8;
    const int gb0 = blockIdx.x * TB;

    const float bh0 = bhh[k], bh1 = bhh[128 + k], bh2 = bhh[256 + k];
    float wr0 = 0, wr1 = 0, wz0 = 0, wz1 = 0, wn0 = 0, wn1 = 0, br = 0, bz = 0, bn = 0;
    if (LAYER == 0) {
        const float* Wih = dir ? Wih_b : Wih_f;
        const float* bih = dir ? bih_b : bih_f;
        wr0 = Wih[k * 2];         wr1 = Wih[k * 2 + 1];
        wz0 = Wih[(128 + k) * 2]; wz1 = Wih[(128 + k) * 2 + 1];
        wn0 = Wih[(256 + k) * 2]; wn1 = Wih[(256 + k) * 2 + 1];
        br = bih[k]; bz = bih[128 + k]; bn = bih[256 + k];
    }
    __syncthreads();

    int cur = 0;
    for (int t = 0; t < SEQ; ++t) {
        const int tt = dir ? (SEQ - 1 - t) : t;
        float* rd = cur ? sh1 : sh0;
        float* wrb = cur ? sh0 : sh1;

        // prefetch input-gate contributions (independent of h; overlaps matmul)
        float xr[8], xz[8], xn[8];
        #pragma unroll
        for (int i = 0; i < 8; ++i) {
            const int gb = gb0 + bbase + i;
            if (LAYER == 0) {
                float c0 = __ldg(&code[(size_t)gb * NLIN + tt * 2 + 0]);
                float c1 = __ldg(&code[(size_t)gb * NLIN + tt * 2 + 1]);
                xr[i] = fmaf(c0, wr0, fmaf(c1, wr1, br));
                xz[i] = fmaf(c0, wz0, fmaf(c1, wz1, bz));
                xn[i] = fmaf(c0, wn0, fmaf(c1, wn1, bn));
            } else {
                size_t base = ((size_t)dir * BL + (size_t)gb * SEQ + tt) * H3;
                xr[i] = __ldg(&xg[base + k]);
                xz[i] = __ldg(&xg[base + 128 + k]);
                xn[i] = __ldg(&xg[base + 256 + k]);
            }
        }

        // hg = h @ Whh^T, packed over batch pairs (pointer-walk, unroll 4)
        ull A0[4], A1[4], A2[4];
        #pragma unroll
        for (int p = 0; p < 4; ++p) { A0[p] = 0ULL; A1[p] = 0ULL; A2[p] = 0ULL; }

        const float* wp = sWt + k;
        const float* hp = rd + bbase;
        #pragma unroll 4
        for (int j = 0; j < HID; ++j) {
            ull w0d = dup2(wp[0]);
            ull w1d = dup2(wp[128]);
            ull w2d = dup2(wp[256]);
            const ull* hq = (const ull*)hp;
            ull h01 = hq[0], h23 = hq[1], h45 = hq[2], h67 = hq[3];
            ffma2(A0[0], h01, w0d); ffma2(A0[1], h23, w0d);
            ffma2(A0[2], h45, w0d); ffma2(A0[3], h67, w0d);
            ffma2(A1[0], h01, w1d); ffma2(A1[1], h23, w1d);
            ffma2(A1[2], h45, w1d); ffma2(A1[3], h67, w1d);
            ffma2(A2[0], h01, w2d); ffma2(A2[1], h23, w2d);
            ffma2(A2[2], h45, w2d); ffma2(A2[3], h67, w2d);
            wp += H3; hp += TB;
        }

        #pragma unroll
        for (int p = 0; p < 4; ++p) {
            float2 a0 = unpk2(A0[p]);
            float2 a1 = unpk2(A1[p]);
            float2 a2 = unpk2(A2[p]);
            float2 hp2 = unpk2(*(const ull*)&rd[k * TB + bbase + 2 * p]);

            int i0 = 2 * p, i1 = 2 * p + 1;
            float r0 = sigf(xr[i0] + a0.x + bh0);
            float z0 = sigf(xz[i0] + a1.x + bh1);
            float n0 = tanhfast(xn[i0] + r0 * (a2.x + bh2));
            float hn0 = (1.f - z0) * n0 + z0 * hp2.x;

            float r1 = sigf(xr[i1] + a0.y + bh0);
            float z1 = sigf(xz[i1] + a1.y + bh1);
            float n1 = tanhfast(xn[i1] + r1 * (a2.y + bh2));
            float hn1 = (1.f - z1) * n1 + z1 * hp2.y;

            *(ull*)&wrb[k * TB + bbase + 2 * p] = pk2(hn0, hn1);

            const size_t row0 = (size_t)(gb0 + bbase + i0) * SEQ + tt;
            const int col = dir * HID + k;
            if (LAYER == 0) {
                __nv_bfloat16 hi0 = __float2bfloat16(hn0);
                __nv_bfloat16 lo0 = __float2bfloat16(hn0 - __bfloat162float(hi0));
                __nv_bfloat16 hi1 = __float2bfloat16(hn1);
                __nv_bfloat16 lo1 = __float2bfloat16(hn1 - __bfloat162float(hi1));
                houtH[row0 * H2 + col] = hi0;
                houtL[row0 * H2 + col] = lo0;
                houtH[(row0 + SEQ) * H2 + col] = hi1;
                houtL[(row0 + SEQ) * H2 + col] = lo1;
            } else {
                houtF[row0 * H2 + col] = hn0;
                houtF[(row0 + SEQ) * H2 + col] = hn1;
            }
        }
        __syncthreads();
        cur ^= 1;
    }
}

// ---------------- final head: out = sigmoid(h1 . Wf + bf) ----------------
__global__ __launch_bounds__(256) void final_kernel(
    const float* __restrict__ h1, const float* __restrict__ Wf,
    const float* __restrict__ bf, float* __restrict__ out)
{
    __shared__ float sW[H2];
    int tid = threadIdx.x;
    sW[tid] = Wf[tid];
    __syncthreads();
    int w = tid >> 5, l = tid & 31;
    size_t row = (size_t)blockIdx.x * 8 + w;
    const float* hr = h1 + row * H2;
    float s = 0.f;
    #pragma unroll
    for (int i = 0; i < 8; ++i)
        s = fmaf(hr[l + i * 32], sW[l + i * 32], s);
    #pragma unroll
    for (int off = 16; off; off >>= 1)
        s += __shfl_xor_sync(0xffffffffu, s, off);
    if (l == 0)
        out[row] = 1.f / (1.f + __expf(-(s + bf[0])));
}

// ---------------- launch ----------------
extern "C" void kernel_launch(void* const* d_in, const int* in_sizes, int n_in,
                              void* d_out, int out_size)
{
    const float* received = (const float*)d_in[0];
    const float* W_lin    = (const float*)d_in[1];
    const float* b_lin    = (const float*)d_in[2];
    const float* Wih0f = (const float*)d_in[3],  *Whh0f = (const float*)d_in[4];
    const float* bih0f = (const float*)d_in[5],  *bhh0f = (const float*)d_in[6];
    const float* Wih0b = (const float*)d_in[7],  *Whh0b = (const float*)d_in[8];
    const float* bih0b = (const float*)d_in[9],  *bhh0b = (const float*)d_in[10];
    const float* Wih1f = (const float*)d_in[11], *Whh1f = (const float*)d_in[12];
    const float* bih1f = (const float*)d_in[13], *bhh1f = (const float*)d_in[14];
    const float* Wih1b = (const float*)d_in[15], *Whh1b = (const float*)d_in[16];
    const float* bih1b = (const float*)d_in[17], *bhh1b = (const float*)d_in[18];
    const float* Wf    = (const float*)d_in[19], *bf    = (const float*)d_in[20];
    float* out = (float*)d_out;

    float *code, *xg1, *h1;
    __nv_bfloat16 *ah, *al;
    cudaGetSymbolAddress((void**)&code, g_code);
    cudaGetSymbolAddress((void**)&ah,   g_ah);
    cudaGetSymbolAddress((void**)&al,   g_al);
    cudaGetSymbolAddress((void**)&xg1,  g_xg1);
    cudaGetSymbolAddress((void**)&h1,   g_h1);

    cudaFuncSetAttribute(gru_kernel<0>, cudaFuncAttributeMaxDynamicSharedMemorySize, (int)SMEM_GRU);
    cudaFuncSetAttribute(gru_kernel<1>, cudaFuncAttributeMaxDynamicSharedMemorySize, (int)SMEM_GRU);
    cudaFuncSetAttribute(xgemm_wmma, cudaFuncAttributeMaxDynamicSharedMemorySize, (int)SMEM_WMMA);

    // 1) dec_linear
    sgemm_nt<<<dim3(BATCH / 64, (NLIN + 63) / 64), 256>>>(
        received, W_lin, b_lin, code, BATCH, NLIN, NLIN);

    // 2) layer-0 bidirectional GRU -> bf16 hi/lo h0
    gru_kernel<0><<<dim3(BATCH / TB, 2), 256, SMEM_GRU>>>(
        code, nullptr, Wih0f, Wih0b, Whh0f, Whh0b, bih0f, bih0b, bhh0f, bhh0b,
        nullptr, ah, al);

    // 3) layer-1 input projections on tensor cores (wmma bf16, both dirs fused)
    xgemm_wmma<<<dim3(12, BL / 128), 256, SMEM_WMMA>>>(
        ah, al, Wih1f, Wih1b, bih1f, bih1b, xg1);

    // 4) layer-1 bidirectional GRU
    gru_kernel<1><<<dim3(BATCH / TB, 2), 256, SMEM_GRU>>>(
        nullptr, xg1, nullptr, nullptr, Whh1f, Whh1b, bih1f, bih1b, bhh1f, bhh1b,
        h1, nullptr, nullptr);

    // 5) output head
    final_kernel<<<BL / 8, 256>>>(h1, Wf, bf, out);
}

// round 6
// speedup vs baseline: 1.4185x; 1.0240x over previous
#include <cuda_runtime.h>
#include <cuda_bf16.h>
#include <mma.h>
#include <math.h>
#include <stdint.h>

using namespace nvcuda;

#define BATCH 1024
#define SEQ   200
#define NLIN  400
#define HID   128
#define H2    256
#define H3    384
#define TB    16
#define BL    (BATCH * SEQ)

typedef unsigned long long ull;

// ---------------- scratch (static device globals; no allocation) ----------------
__device__ float g_code[(size_t)BATCH * NLIN];                 // 1.6 MB
__device__ __nv_bfloat16 g_ah[(size_t)BL * H2];                // 105 MB (h0 hi)
__device__ __nv_bfloat16 g_al[(size_t)BL * H2];                // 105 MB (h0 lo)
__device__ float g_xg1 [(size_t)2 * BL * H3];                  // 629 MB
__device__ float g_h1  [(size_t)BL * H2];                      // 210 MB

__device__ __forceinline__ float sigf(float x) {
    return 1.f / (1.f + __expf(-x));
}
__device__ __forceinline__ float tanhfast(float x) {
    float e = __expf(-2.f * fabsf(x));
    float t = (1.f - e) / (1.f + e);
    return x < 0.f ? -t : t;
}

// ---- packed f32x2 helpers (FFMA2, plain PTX, arch-safe) ----
__device__ __forceinline__ ull pk2(float lo, float hi) {
    ull r; asm("mov.b64 %0, {%1, %2};" : "=l"(r) : "f"(lo), "f"(hi)); return r;
}
__device__ __forceinline__ ull dup2(float x) {
    ull r; asm("mov.b64 %0, {%1, %1};" : "=l"(r) : "f"(x)); return r;
}
__device__ __forceinline__ void ffma2(ull& d, ull a, ull b) {
    asm("fma.rn.f32x2 %0, %1, %2, %0;" : "+l"(d) : "l"(a), "l"(b));
}
__device__ __forceinline__ float2 unpk2(ull v) {
    float2 r; asm("mov.b64 {%0, %1}, %2;" : "=f"(r.x), "=f"(r.y) : "l"(v)); return r;
}

// ---------------- small SGEMM for dec_linear: C[M,N] = A[M,K]*B[N,K]^T + bias ----------------
__global__ __launch_bounds__(256) void sgemm_nt(
    const float* __restrict__ A, const float* __restrict__ B,
    const float* __restrict__ bias, float* __restrict__ C,
    int M, int N, int K)
{
    __shared__ float As[16][65];
    __shared__ float Bs[16][65];
    int tid = threadIdx.x;
    int tx = tid & 15, ty = tid >> 4;
    int bm0 = blockIdx.x * 64, bn0 = blockIdx.y * 64;
    int lrow = tid >> 2;
    int lc4  = (tid & 3) * 4;

    float acc[4][4] = {};

    for (int k0 = 0; k0 < K; k0 += 16) {
        float4 av = *(const float4*)(A + (size_t)(bm0 + lrow) * K + k0 + lc4);
        float4 bv = make_float4(0.f, 0.f, 0.f, 0.f);
        if (bn0 + lrow < N)
            bv = *(const float4*)(B + (size_t)(bn0 + lrow) * K + k0 + lc4);
        As[lc4 + 0][lrow] = av.x; As[lc4 + 1][lrow] = av.y;
        As[lc4 + 2][lrow] = av.z; As[lc4 + 3][lrow] = av.w;
        Bs[lc4 + 0][lrow] = bv.x; Bs[lc4 + 1][lrow] = bv.y;
        Bs[lc4 + 2][lrow] = bv.z; Bs[lc4 + 3][lrow] = bv.w;
        __syncthreads();
        #pragma unroll
        for (int kk = 0; kk < 16; ++kk) {
            float a[4], b[4];
            #pragma unroll
            for (int i = 0; i < 4; ++i) { a[i] = As[kk][ty * 4 + i]; b[i] = Bs[kk][tx * 4 + i]; }
            #pragma unroll
            for (int i = 0; i < 4; ++i)
                #pragma unroll
                for (int j = 0; j < 4; ++j)
                    acc[i][j] = fmaf(a[i], b[j], acc[i][j]);
        }
        __syncthreads();
    }

    #pragma unroll
    for (int i = 0; i < 4; ++i) {
        int row = bm0 + ty * 4 + i;
        #pragma unroll
        for (int j = 0; j < 4; ++j) {
            int col = bn0 + tx * 4 + j;
            if (col < N)
                C[(size_t)row * N + col] = acc[i][j] + bias[col];
        }
    }
}

// ---------------- tensor-core layer-1 projection via wmma bf16 (3-term hi/lo split) ----------------
#define LDW 264
#define LDA 72
#define LDE 68
#define OFF_BIAS 0
#define OFF_WH   256
#define OFF_WL   (OFF_WH + 64 * LDW * 2)
#define OFF_AH   (OFF_WL + 64 * LDW * 2)
#define OFF_AL   (OFF_AH + 128 * LDA * 2)
#define OFF_EPI  (OFF_AL + 128 * LDA * 2)
#define SMEM_WMMA (OFF_EPI + 128 * LDE * 4)

__global__ __launch_bounds__(256, 1) void xgemm_wmma(
    const __nv_bfloat16* __restrict__ Ah, const __nv_bfloat16* __restrict__ Al,
    const float* __restrict__ Bf, const float* __restrict__ Bb,
    const float* __restrict__ biasf, const float* __restrict__ biasb,
    float* __restrict__ C)
{
    extern __shared__ char smem[];
    float* sbias = (float*)(smem + OFF_BIAS);
    __nv_bfloat16* sWh = (__nv_bfloat16*)(smem + OFF_WH);
    __nv_bfloat16* sWl = (__nv_bfloat16*)(smem + OFF_WL);
    __nv_bfloat16* sAh = (__nv_bfloat16*)(smem + OFF_AH);
    __nv_bfloat16* sAl = (__nv_bfloat16*)(smem + OFF_AL);
    float* sEpi = (float*)(smem + OFF_EPI);

    const int tid = threadIdx.x;
    const int wid = tid >> 5;
    const int wm = wid & 3;
    const int wn = wid >> 2;

    const int colt = blockIdx.x;
    const int dir  = (colt >= 6);
    const int ncol0 = (colt - 6 * dir) * 64;
    const float* W = dir ? Bb : Bf;
    const float* bias = dir ? biasb : biasf;
    float* Cb = C + (size_t)dir * BL * H3;
    const size_t m0 = (size_t)blockIdx.y * 128;

    for (int idx = tid; idx < 64 * 256; idx += 256) {
        int n = idx >> 8, k = idx & 255;
        float w = W[(size_t)(ncol0 + n) * H2 + k];
        __nv_bfloat16 hi = __float2bfloat16(w);
        __nv_bfloat16 lo = __float2bfloat16(w - __bfloat162float(hi));
        sWh[n * LDW + k] = hi;
        sWl[n * LDW + k] = lo;
    }
    if (tid < 64) sbias[tid] = bias[ncol0 + tid];

    wmma::fragment<wmma::accumulator, 16, 16, 16, float> acc[2][2];
    #pragma unroll
    for (int i = 0; i < 2; ++i)
        #pragma unroll
        for (int j = 0; j < 2; ++j)
            wmma::fill_fragment(acc[i][j], 0.f);

    for (int kc = 0; kc < 4; ++kc) {
        __syncthreads();
        for (int idx = tid; idx < 128 * 8; idx += 256) {
            int r = idx >> 3, c8 = (idx & 7) * 8;
            size_t g = (m0 + r) * H2 + kc * 64 + c8;
            *(uint4*)&sAh[r * LDA + c8] = *(const uint4*)&Ah[g];
            *(uint4*)&sAl[r * LDA + c8] = *(const uint4*)&Al[g];
        }
        __syncthreads();

        #pragma unroll
        for (int kk = 0; kk < 4; ++kk) {
            wmma::fragment<wmma::matrix_a, 16, 16, 16, __nv_bfloat16, wmma::row_major> fah[2], fal[2];
            wmma::fragment<wmma::matrix_b, 16, 16, 16, __nv_bfloat16, wmma::col_major> fbh[2], fbl[2];
            #pragma unroll
            for (int i = 0; i < 2; ++i) {
                wmma::load_matrix_sync(fah[i], sAh + (wm * 32 + i * 16) * LDA + kk * 16, LDA);
                wmma::load_matrix_sync(fal[i], sAl + (wm * 32 + i * 16) * LDA + kk * 16, LDA);
            }
            #pragma unroll
            for (int j = 0; j < 2; ++j) {
                wmma::load_matrix_sync(fbh[j], sWh + (wn * 32 + j * 16) * LDW + kc * 64 + kk * 16, LDW);
                wmma::load_matrix_sync(fbl[j], sWl + (wn * 32 + j * 16) * LDW + kc * 64 + kk * 16, LDW);
            }
            #pragma unroll
            for (int i = 0; i < 2; ++i)
                #pragma unroll
                for (int j = 0; j < 2; ++j) {
                    wmma::mma_sync(acc[i][j], fah[i], fbh[j], acc[i][j]);
                    wmma::mma_sync(acc[i][j], fah[i], fbl[j], acc[i][j]);
                    wmma::mma_sync(acc[i][j], fal[i], fbh[j], acc[i][j]);
                }
        }
    }

    __syncthreads();
    #pragma unroll
    for (int i = 0; i < 2; ++i)
        #pragma unroll
        for (int j = 0; j < 2; ++j)
            wmma::store_matrix_sync(sEpi + (wm * 32 + i * 16) * LDE + wn * 32 + j * 16,
                                    acc[i][j], LDE, wmma::mem_row_major);
    __syncthreads();
    for (int idx = tid; idx < 128 * 16; idx += 256) {
        int r = idx >> 4, c4 = (idx & 15) * 4;
        float4 v = *(float4*)&sEpi[r * LDE + c4];
        v.x += sbias[c4 + 0]; v.y += sbias[c4 + 1];
        v.z += sbias[c4 + 2]; v.w += sbias[c4 + 3];
        *(float4*)(Cb + (m0 + r) * H3 + ncol0 + c4) = v;
    }
}

// ---------------- persistent bidirectional GRU layer (split-j, 512 threads) ----------------
// 16 warps: jhalf = w>>3 (j 0..63 / 64..127), kwarp = w&3, bgroup = (w>>2)&1.
// half-1 writes partial sums to sPart; half-0 adds + gates.
// smem: sWt 192KB + sh 8KB + sPart 24KB = 224KB
#define NPART (12 * 256)
#define SMEM_GRU ((128 * H3 + 128 * TB) * sizeof(float) + NPART * sizeof(ull))

template <int LAYER>
__global__ __launch_bounds__(512, 1) void gru_kernel(
    const float* __restrict__ code,
    const float* __restrict__ xg,
    const float* __restrict__ Wih_f, const float* __restrict__ Wih_b,
    const float* __restrict__ Whh_f, const float* __restrict__ Whh_b,
    const float* __restrict__ bih_f, const float* __restrict__ bih_b,
    const float* __restrict__ bhh_f, const float* __restrict__ bhh_b,
    float* __restrict__ houtF,
    __nv_bfloat16* __restrict__ houtH,
    __nv_bfloat16* __restrict__ houtL)
{
    extern __shared__ float smemf[];
    float* sWt = smemf;                   // [128][384]: sWt[j][g] = Whh[g][j]
    float* sh  = sWt + 128 * H3;          // [128j? no: [j? ] -> [j][b]: [128? ] actually [j*16+b]
    ull* sPart = (ull*)(sh + 128 * TB);   // [12][256]

    const int dir = blockIdx.y;
    const float* Whh = dir ? Whh_b : Whh_f;
    const float* bhh = dir ? bhh_b : bhh_f;
    const int tid = threadIdx.x;

    for (int idx = tid; idx < 128 * H3; idx += 512) {
        int g = idx >> 7, j = idx & 127;
        sWt[j * H3 + g] = Whh[idx];
    }
    for (int idx = tid; idx < 128 * TB; idx += 512) sh[idx] = 0.f;

    const int w = tid >> 5, l = tid & 31;
    const int jhalf = w >> 3;
    const int k = (w & 3) * 32 + l;
    const int bbase = ((w >> 2) & 1) * 8;
    const int gb0 = blockIdx.x * TB;
    const int pidx = (w & 7) * 32 + l;    // matching slot between halves

    const float bh0 = bhh[k], bh1 = bhh[128 + k], bh2 = bhh[256 + k];
    float wr0 = 0, wr1 = 0, wz0 = 0, wz1 = 0, wn0 = 0, wn1 = 0, br = 0, bz = 0, bn = 0;
    if (LAYER == 0) {
        const float* Wih = dir ? Wih_b : Wih_f;
        const float* bih = dir ? bih_b : bih_f;
        wr0 = Wih[k * 2];         wr1 = Wih[k * 2 + 1];
        wz0 = Wih[(128 + k) * 2]; wz1 = Wih[(128 + k) * 2 + 1];
        wn0 = Wih[(256 + k) * 2]; wn1 = Wih[(256 + k) * 2 + 1];
        br = bih[k]; bz = bih[128 + k]; bn = bih[256 + k];
    }
    const ull one2 = dup2(1.0f);
    __syncthreads();

    for (int t = 0; t < SEQ; ++t) {
        const int tt = dir ? (SEQ - 1 - t) : t;

        // input-gate prefetch (half-0 only; overlaps matmul)
        float xr[8], xz[8], xn[8];
        if (jhalf == 0) {
            #pragma unroll
            for (int i = 0; i < 8; ++i) {
                const int gb = gb0 + bbase + i;
                if (LAYER == 0) {
                    float c0 = __ldg(&code[(size_t)gb * NLIN + tt * 2 + 0]);
                    float c1 = __ldg(&code[(size_t)gb * NLIN + tt * 2 + 1]);
                    xr[i] = fmaf(c0, wr0, fmaf(c1, wr1, br));
                    xz[i] = fmaf(c0, wz0, fmaf(c1, wz1, bz));
                    xn[i] = fmaf(c0, wn0, fmaf(c1, wn1, bn));
                } else {
                    size_t base = ((size_t)dir * BL + (size_t)gb * SEQ + tt) * H3;
                    xr[i] = __ldg(&xg[base + k]);
                    xz[i] = __ldg(&xg[base + 128 + k]);
                    xn[i] = __ldg(&xg[base + 256 + k]);
                }
            }
        }

        // partial hg over this warp's 64 j values
        ull A0[4], A1[4], A2[4];
        #pragma unroll
        for (int p = 0; p < 4; ++p) { A0[p] = 0ULL; A1[p] = 0ULL; A2[p] = 0ULL; }

        const float* wp = sWt + jhalf * 64 * H3 + k;
        const float* hp = sh + jhalf * 64 * TB + bbase;
        #pragma unroll 4
        for (int j = 0; j < 64; ++j) {
            ull w0d = dup2(wp[0]);
            ull w1d = dup2(wp[128]);
            ull w2d = dup2(wp[256]);
            uint4 q0 = *(const uint4*)hp;
            uint4 q1 = *(const uint4*)(hp + 4);
            ull h01 = ((const ull*)&q0)[0], h23 = ((const ull*)&q0)[1];
            ull h45 = ((const ull*)&q1)[0], h67 = ((const ull*)&q1)[1];
            ffma2(A0[0], h01, w0d); ffma2(A0[1], h23, w0d);
            ffma2(A0[2], h45, w0d); ffma2(A0[3], h67, w0d);
            ffma2(A1[0], h01, w1d); ffma2(A1[1], h23, w1d);
            ffma2(A1[2], h45, w1d); ffma2(A1[3], h67, w1d);
            ffma2(A2[0], h01, w2d); ffma2(A2[1], h23, w2d);
            ffma2(A2[2], h45, w2d); ffma2(A2[3], h67, w2d);
            wp += H3; hp += TB;
        }

        if (jhalf == 1) {
            #pragma unroll
            for (int p = 0; p < 4; ++p) {
                sPart[p * 256 + pidx]        = A0[p];
                sPart[(4 + p) * 256 + pidx]  = A1[p];
                sPart[(8 + p) * 256 + pidx]  = A2[p];
            }
        }
        __syncthreads();   // partials visible; all sh reads done

        if (jhalf == 0) {
            #pragma unroll
            for (int p = 0; p < 4; ++p) {
                ffma2(A0[p], sPart[p * 256 + pidx], one2);
                ffma2(A1[p], sPart[(4 + p) * 256 + pidx], one2);
                ffma2(A2[p], sPart[(8 + p) * 256 + pidx], one2);
            }

            #pragma unroll
            for (int p = 0; p < 4; ++p) {
                float2 a0 = unpk2(A0[p]);
                float2 a1 = unpk2(A1[p]);
                float2 a2 = unpk2(A2[p]);
                float2 hp2 = unpk2(*(const ull*)&sh[k * TB + bbase + 2 * p]);

                int i0 = 2 * p, i1 = 2 * p + 1;
                float r0 = sigf(xr[i0] + a0.x + bh0);
                float z0 = sigf(xz[i0] + a1.x + bh1);
                float n0 = tanhfast(xn[i0] + r0 * (a2.x + bh2));
                float hn0 = (1.f - z0) * n0 + z0 * hp2.x;

                float r1 = sigf(xr[i1] + a0.y + bh0);
                float z1 = sigf(xz[i1] + a1.y + bh1);
                float n1 = tanhfast(xn[i1] + r1 * (a2.y + bh2));
                float hn1 = (1.f - z1) * n1 + z1 * hp2.y;

                *(ull*)&sh[k * TB + bbase + 2 * p] = pk2(hn0, hn1);

                const size_t row0 = (size_t)(gb0 + bbase + i0) * SEQ + tt;
                const int col = dir * HID + k;
                if (LAYER == 0) {
                    __nv_bfloat16 hi0 = __float2bfloat16(hn0);
                    __nv_bfloat16 lo0 = __float2bfloat16(hn0 - __bfloat162float(hi0));
                    __nv_bfloat16 hi1 = __float2bfloat16(hn1);
                    __nv_bfloat16 lo1 = __float2bfloat16(hn1 - __bfloat162float(hi1));
                    houtH[row0 * H2 + col] = hi0;
                    houtL[row0 * H2 + col] = lo0;
                    houtH[(row0 + SEQ) * H2 + col] = hi1;
                    houtL[(row0 + SEQ) * H2 + col] = lo1;
                } else {
                    houtF[row0 * H2 + col] = hn0;
                    houtF[(row0 + SEQ) * H2 + col] = hn1;
                }
            }
        }
        __syncthreads();   // new h visible before next step
    }
}

// ---------------- final head: out = sigmoid(h1 . Wf + bf) ----------------
__global__ __launch_bounds__(256) void final_kernel(
    const float* __restrict__ h1, const float* __restrict__ Wf,
    const float* __restrict__ bf, float* __restrict__ out)
{
    __shared__ float sW[H2];
    int tid = threadIdx.x;
    sW[tid] = Wf[tid];
    __syncthreads();
    int w = tid >> 5, l = tid & 31;
    size_t row = (size_t)blockIdx.x * 8 + w;
    const float* hr = h1 + row * H2;
    float s = 0.f;
    #pragma unroll
    for (int i = 0; i < 8; ++i)
        s = fmaf(hr[l + i * 32], sW[l + i * 32], s);
    #pragma unroll
    for (int off = 16; off; off >>= 1)
        s += __shfl_xor_sync(0xffffffffu, s, off);
    if (l == 0)
        out[row] = 1.f / (1.f + __expf(-(s + bf[0])));
}

// ---------------- launch ----------------
extern "C" void kernel_launch(void* const* d_in, const int* in_sizes, int n_in,
                              void* d_out, int out_size)
{
    const float* received = (const float*)d_in[0];
    const float* W_lin    = (const float*)d_in[1];
    const float* b_lin    = (const float*)d_in[2];
    const float* Wih0f = (const float*)d_in[3],  *Whh0f = (const float*)d_in[4];
    const float* bih0f = (const float*)d_in[5],  *bhh0f = (const float*)d_in[6];
    const float* Wih0b = (const float*)d_in[7],  *Whh0b = (const float*)d_in[8];
    const float* bih0b = (const float*)d_in[9],  *bhh0b = (const float*)d_in[10];
    const float* Wih1f = (const float*)d_in[11], *Whh1f = (const float*)d_in[12];
    const float* bih1f = (const float*)d_in[13], *bhh1f = (const float*)d_in[14];
    const float* Wih1b = (const float*)d_in[15], *Whh1b = (const float*)d_in[16];
    const float* bih1b = (const float*)d_in[17], *bhh1b = (const float*)d_in[18];
    const float* Wf    = (const float*)d_in[19], *bf    = (const float*)d_in[20];
    float* out = (float*)d_out;

    float *code, *xg1, *h1;
    __nv_bfloat16 *ah, *al;
    cudaGetSymbolAddress((void**)&code, g_code);
    cudaGetSymbolAddress((void**)&ah,   g_ah);
    cudaGetSymbolAddress((void**)&al,   g_al);
    cudaGetSymbolAddress((void**)&xg1,  g_xg1);
    cudaGetSymbolAddress((void**)&h1,   g_h1);

    cudaFuncSetAttribute(gru_kernel<0>, cudaFuncAttributeMaxDynamicSharedMemorySize, (int)SMEM_GRU);
    cudaFuncSetAttribute(gru_kernel<1>, cudaFuncAttributeMaxDynamicSharedMemorySize, (int)SMEM_GRU);
    cudaFuncSetAttribute(xgemm_wmma, cudaFuncAttributeMaxDynamicSharedMemorySize, (int)SMEM_WMMA);

    // 1) dec_linear
    sgemm_nt<<<dim3(BATCH / 64, (NLIN + 63) / 64), 256>>>(
        received, W_lin, b_lin, code, BATCH, NLIN, NLIN);

    // 2) layer-0 bidirectional GRU -> bf16 hi/lo h0
    gru_kernel<0><<<dim3(BATCH / TB, 2), 512, SMEM_GRU>>>(
        code, nullptr, Wih0f, Wih0b, Whh0f, Whh0b, bih0f, bih0b, bhh0f, bhh0b,
        nullptr, ah, al);

    // 3) layer-1 input projections on tensor cores (wmma bf16, both dirs fused)
    xgemm_wmma<<<dim3(12, BL / 128), 256, SMEM_WMMA>>>(
        ah, al, Wih1f, Wih1b, bih1f, bih1b, xg1);

    // 4) layer-1 bidirectional GRU
    gru_kernel<1><<<dim3(BATCH / TB, 2), 512, SMEM_GRU>>>(
        nullptr, xg1, nullptr, nullptr, Whh1f, Whh1b, bih1f, bih1b, bhh1f, bhh1b,
        h1, nullptr, nullptr);

    // 5) output head
    final_kernel<<<BL / 8, 256>>>(h1, Wf, bf, out);
}

// round 7
// speedup vs baseline: 1.6993x; 1.1980x over previous
#include <cuda_runtime.h>
#include <cuda_bf16.h>
#include <mma.h>
#include <math.h>
#include <stdint.h>

using namespace nvcuda;

#define BATCH 1024
#define SEQ   200
#define NLIN  400
#define HID   128
#define H2    256
#define H3    384
#define TB    16
#define BL    (BATCH * SEQ)

typedef unsigned long long ull;

// ---------------- scratch (static device globals; no allocation) ----------------
__device__ float g_code[(size_t)BATCH * NLIN];
__device__ __nv_bfloat16 g_ah[(size_t)BL * H2];
__device__ __nv_bfloat16 g_al[(size_t)BL * H2];
__device__ float g_xg1 [(size_t)2 * BL * H3];
__device__ float g_h1  [(size_t)BL * H2];

__device__ __forceinline__ float sigf(float x) {
    return 1.f / (1.f + __expf(-x));
}
__device__ __forceinline__ float tanhfast(float x) {
    float e = __expf(-2.f * fabsf(x));
    float t = (1.f - e) / (1.f + e);
    return x < 0.f ? -t : t;
}

// ---------------- small SGEMM for dec_linear ----------------
__global__ __launch_bounds__(256) void sgemm_nt(
    const float* __restrict__ A, const float* __restrict__ B,
    const float* __restrict__ bias, float* __restrict__ C,
    int M, int N, int K)
{
    __shared__ float As[16][65];
    __shared__ float Bs[16][65];
    int tid = threadIdx.x;
    int tx = tid & 15, ty = tid >> 4;
    int bm0 = blockIdx.x * 64, bn0 = blockIdx.y * 64;
    int lrow = tid >> 2;
    int lc4  = (tid & 3) * 4;

    float acc[4][4] = {};

    for (int k0 = 0; k0 < K; k0 += 16) {
        float4 av = *(const float4*)(A + (size_t)(bm0 + lrow) * K + k0 + lc4);
        float4 bv = make_float4(0.f, 0.f, 0.f, 0.f);
        if (bn0 + lrow < N)
            bv = *(const float4*)(B + (size_t)(bn0 + lrow) * K + k0 + lc4);
        As[lc4 + 0][lrow] = av.x; As[lc4 + 1][lrow] = av.y;
        As[lc4 + 2][lrow] = av.z; As[lc4 + 3][lrow] = av.w;
        Bs[lc4 + 0][lrow] = bv.x; Bs[lc4 + 1][lrow] = bv.y;
        Bs[lc4 + 2][lrow] = bv.z; Bs[lc4 + 3][lrow] = bv.w;
        __syncthreads();
        #pragma unroll
        for (int kk = 0; kk < 16; ++kk) {
            float a[4], b[4];
            #pragma unroll
            for (int i = 0; i < 4; ++i) { a[i] = As[kk][ty * 4 + i]; b[i] = Bs[kk][tx * 4 + i]; }
            #pragma unroll
            for (int i = 0; i < 4; ++i)
                #pragma unroll
                for (int j = 0; j < 4; ++j)
                    acc[i][j] = fmaf(a[i], b[j], acc[i][j]);
        }
        __syncthreads();
    }

    #pragma unroll
    for (int i = 0; i < 4; ++i) {
        int row = bm0 + ty * 4 + i;
        #pragma unroll
        for (int j = 0; j < 4; ++j) {
            int col = bn0 + tx * 4 + j;
            if (col < N)
                C[(size_t)row * N + col] = acc[i][j] + bias[col];
        }
    }
}

// ---------------- tensor-core layer-1 projection via wmma bf16 (3-term split) ----------------
#define LDW 264
#define LDA 72
#define LDE 68
#define OFF_BIAS 0
#define OFF_WH   256
#define OFF_WL   (OFF_WH + 64 * LDW * 2)
#define OFF_AH   (OFF_WL + 64 * LDW * 2)
#define OFF_AL   (OFF_AH + 128 * LDA * 2)
#define OFF_EPI  (OFF_AL + 128 * LDA * 2)
#define SMEM_WMMA (OFF_EPI + 128 * LDE * 4)

__global__ __launch_bounds__(256, 1) void xgemm_wmma(
    const __nv_bfloat16* __restrict__ Ah, const __nv_bfloat16* __restrict__ Al,
    const float* __restrict__ Bf, const float* __restrict__ Bb,
    const float* __restrict__ biasf, const float* __restrict__ biasb,
    float* __restrict__ C)
{
    extern __shared__ char smem[];
    float* sbias = (float*)(smem + OFF_BIAS);
    __nv_bfloat16* sWh = (__nv_bfloat16*)(smem + OFF_WH);
    __nv_bfloat16* sWl = (__nv_bfloat16*)(smem + OFF_WL);
    __nv_bfloat16* sAh = (__nv_bfloat16*)(smem + OFF_AH);
    __nv_bfloat16* sAl = (__nv_bfloat16*)(smem + OFF_AL);
    float* sEpi = (float*)(smem + OFF_EPI);

    const int tid = threadIdx.x;
    const int wid = tid >> 5;
    const int wm = wid & 3;
    const int wn = wid >> 2;

    const int colt = blockIdx.x;
    const int dir  = (colt >= 6);
    const int ncol0 = (colt - 6 * dir) * 64;
    const float* W = dir ? Bb : Bf;
    const float* bias = dir ? biasb : biasf;
    float* Cb = C + (size_t)dir * BL * H3;
    const size_t m0 = (size_t)blockIdx.y * 128;

    for (int idx = tid; idx < 64 * 256; idx += 256) {
        int n = idx >> 8, k = idx & 255;
        float w = W[(size_t)(ncol0 + n) * H2 + k];
        __nv_bfloat16 hi = __float2bfloat16(w);
        __nv_bfloat16 lo = __float2bfloat16(w - __bfloat162float(hi));
        sWh[n * LDW + k] = hi;
        sWl[n * LDW + k] = lo;
    }
    if (tid < 64) sbias[tid] = bias[ncol0 + tid];

    wmma::fragment<wmma::accumulator, 16, 16, 16, float> acc[2][2];
    #pragma unroll
    for (int i = 0; i < 2; ++i)
        #pragma unroll
        for (int j = 0; j < 2; ++j)
            wmma::fill_fragment(acc[i][j], 0.f);

    for (int kc = 0; kc < 4; ++kc) {
        __syncthreads();
        for (int idx = tid; idx < 128 * 8; idx += 256) {
            int r = idx >> 3, c8 = (idx & 7) * 8;
            size_t g = (m0 + r) * H2 + kc * 64 + c8;
            *(uint4*)&sAh[r * LDA + c8] = *(const uint4*)&Ah[g];
            *(uint4*)&sAl[r * LDA + c8] = *(const uint4*)&Al[g];
        }
        __syncthreads();

        #pragma unroll
        for (int kk = 0; kk < 4; ++kk) {
            wmma::fragment<wmma::matrix_a, 16, 16, 16, __nv_bfloat16, wmma::row_major> fah[2], fal[2];
            wmma::fragment<wmma::matrix_b, 16, 16, 16, __nv_bfloat16, wmma::col_major> fbh[2], fbl[2];
            #pragma unroll
            for (int i = 0; i < 2; ++i) {
                wmma::load_matrix_sync(fah[i], sAh + (wm * 32 + i * 16) * LDA + kk * 16, LDA);
                wmma::load_matrix_sync(fal[i], sAl + (wm * 32 + i * 16) * LDA + kk * 16, LDA);
            }
            #pragma unroll
            for (int j = 0; j < 2; ++j) {
                wmma::load_matrix_sync(fbh[j], sWh + (wn * 32 + j * 16) * LDW + kc * 64 + kk * 16, LDW);
                wmma::load_matrix_sync(fbl[j], sWl + (wn * 32 + j * 16) * LDW + kc * 64 + kk * 16, LDW);
            }
            #pragma unroll
            for (int i = 0; i < 2; ++i)
                #pragma unroll
                for (int j = 0; j < 2; ++j) {
                    wmma::mma_sync(acc[i][j], fah[i], fbh[j], acc[i][j]);
                    wmma::mma_sync(acc[i][j], fah[i], fbl[j], acc[i][j]);
                    wmma::mma_sync(acc[i][j], fal[i], fbh[j], acc[i][j]);
                }
        }
    }

    __syncthreads();
    #pragma unroll
    for (int i = 0; i < 2; ++i)
        #pragma unroll
        for (int j = 0; j < 2; ++j)
            wmma::store_matrix_sync(sEpi + (wm * 32 + i * 16) * LDE + wn * 32 + j * 16,
                                    acc[i][j], LDE, wmma::mem_row_major);
    __syncthreads();
    for (int idx = tid; idx < 128 * 16; idx += 256) {
        int r = idx >> 4, c4 = (idx & 15) * 4;
        float4 v = *(float4*)&sEpi[r * LDE + c4];
        v.x += sbias[c4 + 0]; v.y += sbias[c4 + 1];
        v.z += sbias[c4 + 2]; v.w += sbias[c4 + 3];
        *(float4*)(Cb + (m0 + r) * H3 + ncol0 + c4) = v;
    }
}

// ---------------- tensor-core GRU layer ----------------
// Per CTA: 16 batch x 1 dir, 512 threads (16 warps; warp w = batch row w).
// Whh stored gate-interleaved (col' = 3k+g), bf16 hi/lo, k-chunked (2 x 192 cols').
// h fp32 master in regs (thread = (b=wid, k pair per lane per chunk)).
#define LDWP 392
#define LDH  136
#define LDEPI 196
#define GOFF_WH  0
#define GOFF_WL  (GOFF_WH + 128 * LDWP * 2)                // 100352
#define GOFF_HH  (GOFF_WL + 128 * LDWP * 2)                // 200704
#define GOFF_HL  (GOFF_HH + TB * LDH * 2)                  // 205056
#define GOFF_EPI (GOFF_HL + TB * LDH * 2)                  // 209408
#define GOFF_BHH (GOFF_EPI + TB * LDEPI * 4)               // 221952
#define GOFF_BIH (GOFF_BHH + H3 * 4)                       // 223488
#define GOFF_WIH (GOFF_BIH + H3 * 4)                       // 225024
#define SMEM_GRUTC (GOFF_WIH + H3 * 2 * 4)                 // 228096

template <int LAYER>
__global__ __launch_bounds__(512, 1) void gru_tc(
    const float* __restrict__ code,
    const float* __restrict__ xg,
    const float* __restrict__ Wih_f, const float* __restrict__ Wih_b,
    const float* __restrict__ Whh_f, const float* __restrict__ Whh_b,
    const float* __restrict__ bih_f, const float* __restrict__ bih_b,
    const float* __restrict__ bhh_f, const float* __restrict__ bhh_b,
    float* __restrict__ houtF,
    __nv_bfloat16* __restrict__ houtH,
    __nv_bfloat16* __restrict__ houtL)
{
    extern __shared__ char smem[];
    __nv_bfloat16* sWh = (__nv_bfloat16*)(smem + GOFF_WH);
    __nv_bfloat16* sWl = (__nv_bfloat16*)(smem + GOFF_WL);
    __nv_bfloat16* sHh = (__nv_bfloat16*)(smem + GOFF_HH);
    __nv_bfloat16* sHl = (__nv_bfloat16*)(smem + GOFF_HL);
    float* sEpi = (float*)(smem + GOFF_EPI);
    float* sBhh = (float*)(smem + GOFF_BHH);
    float* sBih = (float*)(smem + GOFF_BIH);
    float* sWih = (float*)(smem + GOFF_WIH);

    const int tid = threadIdx.x;
    const int dir = blockIdx.y;
    const int gb0 = blockIdx.x * TB;
    const float* Whh = dir ? Whh_b : Whh_f;
    const float* bhh = dir ? bhh_b : bhh_f;

    // Whh -> permuted bf16 hi/lo: sWh[j][ (k>>6)*192 + 3*(k&63) + g ]
    for (int idx = tid; idx < H3 * HID; idx += 512) {
        int r = idx >> 7, j = idx & 127;        // r = g*128 + k
        int g = r >> 7, k = r & 127;
        int colp = (k >> 6) * 192 + 3 * (k & 63) + g;
        float w = Whh[r * HID + j];
        __nv_bfloat16 hi = __float2bfloat16(w);
        __nv_bfloat16 lo = __float2bfloat16(w - __bfloat162float(hi));
        sWh[j * LDWP + colp] = hi;
        sWl[j * LDWP + colp] = lo;
    }
    for (int idx = tid; idx < H3; idx += 512) {
        sBhh[idx] = bhh[idx];
        if (LAYER == 0) {
            const float* Wih = dir ? Wih_b : Wih_f;
            const float* bih = dir ? bih_b : bih_f;
            sBih[idx] = bih[idx];
            sWih[idx * 2 + 0] = Wih[idx * 2 + 0];
            sWih[idx * 2 + 1] = Wih[idx * 2 + 1];
        }
    }
    for (int idx = tid; idx < TB * LDH; idx += 512) {
        sHh[idx] = __float2bfloat16(0.f);
        sHl[idx] = __float2bfloat16(0.f);
    }
    __syncthreads();

    const int wid = tid >> 5, lane = tid & 31;
    const int b = wid;                     // batch row within tile
    const int k0 = lane * 2;               // chunk0 ks: k0, k0+1; chunk1: 64+k0, 64+k0+1
    // h state: [0]=k0, [1]=k0+1 (chunk0), [2]=64+k0, [3]=64+k0+1 (chunk1)
    float h[4] = {0.f, 0.f, 0.f, 0.f};

    for (int t = 0; t < SEQ; ++t) {
        const int tt = dir ? (SEQ - 1 - t) : t;

        // ---- prefetch input-gate terms (global loads; latency hidden by mma) ----
        float xr[4], xz[4], xn[4];
        if (LAYER == 1) {
            const float* xp = xg + ((size_t)dir * BL + (size_t)(gb0 + b) * SEQ + tt) * H3;
            float2 v;
            v = *(const float2*)(xp + k0);            xr[0] = v.x; xr[1] = v.y;
            v = *(const float2*)(xp + 64 + k0);       xr[2] = v.x; xr[3] = v.y;
            v = *(const float2*)(xp + 128 + k0);      xz[0] = v.x; xz[1] = v.y;
            v = *(const float2*)(xp + 192 + k0);      xz[2] = v.x; xz[3] = v.y;
            v = *(const float2*)(xp + 256 + k0);      xn[0] = v.x; xn[1] = v.y;
            v = *(const float2*)(xp + 320 + k0);      xn[2] = v.x; xn[3] = v.y;
        } else {
            float c0 = __ldg(&code[(size_t)(gb0 + b) * NLIN + tt * 2 + 0]);
            float c1 = __ldg(&code[(size_t)(gb0 + b) * NLIN + tt * 2 + 1]);
            #pragma unroll
            for (int i = 0; i < 4; ++i) {
                int k = (i >> 1) * 64 + k0 + (i & 1);
                xr[i] = fmaf(c0, sWih[k * 2],           fmaf(c1, sWih[k * 2 + 1],           sBih[k]));
                xz[i] = fmaf(c0, sWih[(128 + k) * 2],   fmaf(c1, sWih[(128 + k) * 2 + 1],   sBih[128 + k]));
                xn[i] = fmaf(c0, sWih[(256 + k) * 2],   fmaf(c1, sWih[(256 + k) * 2 + 1],   sBih[256 + k]));
            }
        }

        // ---- mma chunk 0 (a-frags loaded once, persist for chunk 1) ----
        wmma::fragment<wmma::matrix_a, 16, 16, 16, __nv_bfloat16, wmma::row_major> aH[8], aL[8];
        if (wid < 12) {
            wmma::fragment<wmma::accumulator, 16, 16, 16, float> acc;
            wmma::fill_fragment(acc, 0.f);
            #pragma unroll
            for (int jf = 0; jf < 8; ++jf) {
                wmma::fragment<wmma::matrix_b, 16, 16, 16, __nv_bfloat16, wmma::row_major> bH, bL;
                wmma::load_matrix_sync(aH[jf], sHh + jf * 16, LDH);
                wmma::load_matrix_sync(aL[jf], sHl + jf * 16, LDH);
                wmma::load_matrix_sync(bH, sWh + (jf * 16) * LDWP + wid * 16, LDWP);
                wmma::load_matrix_sync(bL, sWl + (jf * 16) * LDWP + wid * 16, LDWP);
                wmma::mma_sync(acc, aH[jf], bH, acc);
                wmma::mma_sync(acc, aH[jf], bL, acc);
                wmma::mma_sync(acc, aL[jf], bH, acc);
            }
            wmma::store_matrix_sync(sEpi + wid * 16, acc, LDEPI, wmma::mem_row_major);
        }
        __syncthreads();

        // ---- gates chunk 0 (k = k0, k0+1), h update in regs only ----
        #pragma unroll
        for (int i = 0; i < 2; ++i) {
            int k = k0 + i;                       // 0..63
            const float* e = sEpi + b * LDEPI + 3 * k;
            float r = sigf(xr[i] + e[0] + sBhh[k]);
            float z = sigf(xz[i] + e[1] + sBhh[128 + k]);
            float n = tanhfast(xn[i] + r * (e[2] + sBhh[256 + k]));
            h[i] = (1.f - z) * n + z * h[i];
        }
        __syncthreads();   // epi free for chunk 1

        // ---- mma chunk 1 (reuses persisted a-frags; sHh/sHl still OLD) ----
        if (wid < 12) {
            wmma::fragment<wmma::accumulator, 16, 16, 16, float> acc;
            wmma::fill_fragment(acc, 0.f);
            #pragma unroll
            for (int jf = 0; jf < 8; ++jf) {
                wmma::fragment<wmma::matrix_b, 16, 16, 16, __nv_bfloat16, wmma::row_major> bH, bL;
                wmma::load_matrix_sync(bH, sWh + (jf * 16) * LDWP + 192 + wid * 16, LDWP);
                wmma::load_matrix_sync(bL, sWl + (jf * 16) * LDWP + 192 + wid * 16, LDWP);
                wmma::mma_sync(acc, aH[jf], bH, acc);
                wmma::mma_sync(acc, aH[jf], bL, acc);
                wmma::mma_sync(acc, aL[jf], bH, acc);
            }
            wmma::store_matrix_sync(sEpi + wid * 16, acc, LDEPI, wmma::mem_row_major);
        }
        __syncthreads();

        // ---- gates chunk 1 (k = 64+k0, 64+k0+1) ----
        #pragma unroll
        for (int i = 0; i < 2; ++i) {
            int kk = k0 + i;                      // local 0..63
            int k = 64 + kk;
            const float* e = sEpi + b * LDEPI + 3 * kk;
            float r = sigf(xr[2 + i] + e[0] + sBhh[k]);
            float z = sigf(xz[2 + i] + e[1] + sBhh[128 + k]);
            float n = tanhfast(xn[2 + i] + r * (e[2] + sBhh[256 + k]));
            h[2 + i] = (1.f - z) * n + z * h[2 + i];
        }

        // ---- writeback: new h -> sHh/sHl + global hout ----
        const size_t orow = ((size_t)(gb0 + b) * SEQ + tt) * H2 + dir * HID;
        #pragma unroll
        for (int i = 0; i < 4; ++i) {
            int k = (i >> 1) * 64 + k0 + (i & 1);
            float v = h[i];
            __nv_bfloat16 hi = __float2bfloat16(v);
            __nv_bfloat16 lo = __float2bfloat16(v - __bfloat162float(hi));
            sHh[b * LDH + k] = hi;
            sHl[b * LDH + k] = lo;
            if (LAYER == 0) {
                houtH[orow + k] = hi;
                houtL[orow + k] = lo;
            } else {
                houtF[orow + k] = v;
            }
        }
        __syncthreads();   // new h visible before next step's mma
    }
}

// ---------------- final head ----------------
__global__ __launch_bounds__(256) void final_kernel(
    const float* __restrict__ h1, const float* __restrict__ Wf,
    const float* __restrict__ bf, float* __restrict__ out)
{
    __shared__ float sW[H2];
    int tid = threadIdx.x;
    sW[tid] = Wf[tid];
    __syncthreads();
    int w = tid >> 5, l = tid & 31;
    size_t row = (size_t)blockIdx.x * 8 + w;
    const float* hr = h1 + row * H2;
    float s = 0.f;
    #pragma unroll
    for (int i = 0; i < 8; ++i)
        s = fmaf(hr[l + i * 32], sW[l + i * 32], s);
    #pragma unroll
    for (int off = 16; off; off >>= 1)
        s += __shfl_xor_sync(0xffffffffu, s, off);
    if (l == 0)
        out[row] = 1.f / (1.f + __expf(-(s + bf[0])));
}

// ---------------- launch ----------------
extern "C" void kernel_launch(void* const* d_in, const int* in_sizes, int n_in,
                              void* d_out, int out_size)
{
    const float* received = (const float*)d_in[0];
    const float* W_lin    = (const float*)d_in[1];
    const float* b_lin    = (const float*)d_in[2];
    const float* Wih0f = (const float*)d_in[3],  *Whh0f = (const float*)d_in[4];
    const float* bih0f = (const float*)d_in[5],  *bhh0f = (const float*)d_in[6];
    const float* Wih0b = (const float*)d_in[7],  *Whh0b = (const float*)d_in[8];
    const float* bih0b = (const float*)d_in[9],  *bhh0b = (const float*)d_in[10];
    const float* Wih1f = (const float*)d_in[11], *Whh1f = (const float*)d_in[12];
    const float* bih1f = (const float*)d_in[13], *bhh1f = (const float*)d_in[14];
    const float* Wih1b = (const float*)d_in[15], *Whh1b = (const float*)d_in[16];
    const float* bih1b = (const float*)d_in[17], *bhh1b = (const float*)d_in[18];
    const float* Wf    = (const float*)d_in[19], *bf    = (const float*)d_in[20];
    float* out = (float*)d_out;

    float *code, *xg1, *h1;
    __nv_bfloat16 *ah, *al;
    cudaGetSymbolAddress((void**)&code, g_code);
    cudaGetSymbolAddress((void**)&ah,   g_ah);
    cudaGetSymbolAddress((void**)&al,   g_al);
    cudaGetSymbolAddress((void**)&xg1,  g_xg1);
    cudaGetSymbolAddress((void**)&h1,   g_h1);

    cudaFuncSetAttribute(gru_tc<0>, cudaFuncAttributeMaxDynamicSharedMemorySize, (int)SMEM_GRUTC);
    cudaFuncSetAttribute(gru_tc<1>, cudaFuncAttributeMaxDynamicSharedMemorySize, (int)SMEM_GRUTC);
    cudaFuncSetAttribute(xgemm_wmma, cudaFuncAttributeMaxDynamicSharedMemorySize, (int)SMEM_WMMA);

    // 1) dec_linear
    sgemm_nt<<<dim3(BATCH / 64, (NLIN + 63) / 64), 256>>>(
        received, W_lin, b_lin, code, BATCH, NLIN, NLIN);

    // 2) layer-0 bidirectional GRU (tensor-core recurrence) -> bf16 hi/lo h0
    gru_tc<0><<<dim3(BATCH / TB, 2), 512, SMEM_GRUTC>>>(
        code, nullptr, Wih0f, Wih0b, Whh0f, Whh0b, bih0f, bih0b, bhh0f, bhh0b,
        nullptr, ah, al);

    // 3) layer-1 input projections (wmma bf16, both dirs fused)
    xgemm_wmma<<<dim3(12, BL / 128), 256, SMEM_WMMA>>>(
        ah, al, Wih1f, Wih1b, bih1f, bih1b, xg1);

    // 4) layer-1 bidirectional GRU (tensor-core recurrence)
    gru_tc<1><<<dim3(BATCH / TB, 2), 512, SMEM_GRUTC>>>(
        nullptr, xg1, nullptr, nullptr, Whh1f, Whh1b, bih1f, bih1b, bhh1f, bhh1b,
        h1, nullptr, nullptr);

    // 5) output head
    final_kernel<<<BL / 8, 256>>>(h1, Wf, bf, out);
}

// round 8
// speedup vs baseline: 2.4252x; 1.4272x over previous
#include <cuda_runtime.h>
#include <cuda_bf16.h>
#include <mma.h>
#include <math.h>
#include <stdint.h>

using namespace nvcuda;

#define BATCH 1024
#define SEQ   200
#define NLIN  400
#define HID   128
#define H2    256
#define H3    384
#define TB    16
#define BL    (BATCH * SEQ)

typedef unsigned long long ull;

// ---------------- scratch (static device globals; no allocation) ----------------
__device__ float g_code[(size_t)BATCH * NLIN];
__device__ __nv_bfloat16 g_ah[(size_t)BL * H2];
__device__ __nv_bfloat16 g_al[(size_t)BL * H2];
__device__ float g_xg1 [(size_t)2 * BL * H3];
__device__ float g_h1  [(size_t)BL * H2];

__device__ __forceinline__ float sigf(float x) {
    return 1.f / (1.f + __expf(-x));
}
__device__ __forceinline__ float tanhfast(float x) {
    float e = __expf(-2.f * fabsf(x));
    float t = (1.f - e) / (1.f + e);
    return x < 0.f ? -t : t;
}

// ---------------- small SGEMM for dec_linear ----------------
__global__ __launch_bounds__(256) void sgemm_nt(
    const float* __restrict__ A, const float* __restrict__ B,
    const float* __restrict__ bias, float* __restrict__ C,
    int M, int N, int K)
{
    __shared__ float As[16][65];
    __shared__ float Bs[16][65];
    int tid = threadIdx.x;
    int tx = tid & 15, ty = tid >> 4;
    int bm0 = blockIdx.x * 64, bn0 = blockIdx.y * 64;
    int lrow = tid >> 2;
    int lc4  = (tid & 3) * 4;

    float acc[4][4] = {};

    for (int k0 = 0; k0 < K; k0 += 16) {
        float4 av = *(const float4*)(A + (size_t)(bm0 + lrow) * K + k0 + lc4);
        float4 bv = make_float4(0.f, 0.f, 0.f, 0.f);
        if (bn0 + lrow < N)
            bv = *(const float4*)(B + (size_t)(bn0 + lrow) * K + k0 + lc4);
        As[lc4 + 0][lrow] = av.x; As[lc4 + 1][lrow] = av.y;
        As[lc4 + 2][lrow] = av.z; As[lc4 + 3][lrow] = av.w;
        Bs[lc4 + 0][lrow] = bv.x; Bs[lc4 + 1][lrow] = bv.y;
        Bs[lc4 + 2][lrow] = bv.z; Bs[lc4 + 3][lrow] = bv.w;
        __syncthreads();
        #pragma unroll
        for (int kk = 0; kk < 16; ++kk) {
            float a[4], b[4];
            #pragma unroll
            for (int i = 0; i < 4; ++i) { a[i] = As[kk][ty * 4 + i]; b[i] = Bs[kk][tx * 4 + i]; }
            #pragma unroll
            for (int i = 0; i < 4; ++i)
                #pragma unroll
                for (int j = 0; j < 4; ++j)
                    acc[i][j] = fmaf(a[i], b[j], acc[i][j]);
        }
        __syncthreads();
    }

    #pragma unroll
    for (int i = 0; i < 4; ++i) {
        int row = bm0 + ty * 4 + i;
        #pragma unroll
        for (int j = 0; j < 4; ++j) {
            int col = bn0 + tx * 4 + j;
            if (col < N)
                C[(size_t)row * N + col] = acc[i][j] + bias[col];
        }
    }
}

// ---------------- layer-1 projection GEMM v2 (wmma bf16, 3-term hi/lo) ----------------
// C[2][BL][384] = h0[BL][256] @ Wih1{f,b}[384][256]^T + bias.
// grid (6, 200): x -> (dir, 128-col group), y (+200*it, it<8) -> 128-row tile.
// 256 threads = 8 warps (4M x 2N), warp tile 32x64. W resident in smem for all 8 row tiles.
// A chunks (k=32) prefetched to registers during previous chunk's mma.
#define LDW2 264
#define LDA2 40
#define LDE2 132
#define X2_BIAS 0
#define X2_WH   512
#define X2_WL   (X2_WH + 128 * LDW2 * 2)       // +67584
#define X2_AH   (X2_WL + 128 * LDW2 * 2)
#define X2_AL   (X2_AH + 128 * LDA2 * 2)       // +10240
#define X2_EPI  (X2_AL + 128 * LDA2 * 2)
#define SMEM_X2 (X2_EPI + 128 * LDE2 * 4)      // 223744 bytes

__global__ __launch_bounds__(256, 1) void xgemm2(
    const __nv_bfloat16* __restrict__ Ah, const __nv_bfloat16* __restrict__ Al,
    const float* __restrict__ Bf, const float* __restrict__ Bb,
    const float* __restrict__ biasf, const float* __restrict__ biasb,
    float* __restrict__ C)
{
    extern __shared__ char smem[];
    float* sBias = (float*)(smem + X2_BIAS);
    __nv_bfloat16* sWh = (__nv_bfloat16*)(smem + X2_WH);   // [128][LDW2] n-major
    __nv_bfloat16* sWl = (__nv_bfloat16*)(smem + X2_WL);
    __nv_bfloat16* sAh = (__nv_bfloat16*)(smem + X2_AH);   // [128][LDA2] (k=32 chunk)
    __nv_bfloat16* sAl = (__nv_bfloat16*)(smem + X2_AL);
    float* sEpi = (float*)(smem + X2_EPI);                 // [128][LDE2]

    const int tid = threadIdx.x;
    const int wid = tid >> 5;
    const int wm = wid & 3;          // row group: wm*32
    const int wn = wid >> 2;         // col group: wn*64

    const int bx = blockIdx.x;
    const int dir = bx / 3;
    const int ncol0 = (bx % 3) * 128;
    const float* W = dir ? Bb : Bf;
    const float* bias = dir ? biasb : biasf;
    float* Cb = C + (size_t)dir * BL * H3;

    // ---- W tile (128 out-cols x 256 k) -> bf16 hi/lo in smem, once per CTA ----
    for (int idx = tid; idx < 128 * 256; idx += 256) {
        int n = idx >> 8, k = idx & 255;
        float w = W[(size_t)(ncol0 + n) * H2 + k];
        __nv_bfloat16 hi = __float2bfloat16(w);
        __nv_bfloat16 lo = __float2bfloat16(w - __bfloat162float(hi));
        sWh[n * LDW2 + k] = hi;
        sWl[n * LDW2 + k] = lo;
    }
    if (tid < 128) sBias[tid] = bias[ncol0 + tid];

    // per-thread A prefetch mapping: row r, 16 contiguous bf16 starting at cbase
    const int pr = tid >> 1;
    const int cbase = (tid & 1) * 16;

    wmma::fragment<wmma::accumulator, 16, 16, 16, float> acc[2][4];
    #pragma unroll
    for (int i = 0; i < 2; ++i)
        #pragma unroll
        for (int j = 0; j < 4; ++j)
            wmma::fill_fragment(acc[i][j], 0.f);

    // prefetch chunk 0 of row-tile 0
    uint4 ph0, ph1, pl0, pl1;
    {
        size_t g = (size_t)blockIdx.y * 128 * H2 + (size_t)pr * H2 + cbase;
        ph0 = *(const uint4*)(Ah + g);     ph1 = *(const uint4*)(Ah + g + 8);
        pl0 = *(const uint4*)(Al + g);     pl1 = *(const uint4*)(Al + g + 8);
    }

    for (int it = 0; it < 8; ++it) {
        const size_t m0 = ((size_t)it * 200 + blockIdx.y) * 128;

        for (int c = 0; c < 8; ++c) {
            __syncthreads();   // previous chunk's mma / previous epilogue done
            *(uint4*)&sAh[pr * LDA2 + cbase]     = ph0;
            *(uint4*)&sAh[pr * LDA2 + cbase + 8] = ph1;
            *(uint4*)&sAl[pr * LDA2 + cbase]     = pl0;
            *(uint4*)&sAl[pr * LDA2 + cbase + 8] = pl1;

            // issue prefetch for next chunk (completes under this chunk's mma)
            if (c < 7 || it < 7) {
                int nc = (c < 7) ? c + 1 : 0;
                size_t nm0 = (c < 7) ? m0 : ((size_t)(it + 1) * 200 + blockIdx.y) * 128;
                size_t g = (nm0 + pr) * H2 + nc * 32 + cbase;
                ph0 = *(const uint4*)(Ah + g);     ph1 = *(const uint4*)(Ah + g + 8);
                pl0 = *(const uint4*)(Al + g);     pl1 = *(const uint4*)(Al + g + 8);
            }
            __syncthreads();   // sA ready

            #pragma unroll
            for (int kk = 0; kk < 2; ++kk) {
                wmma::fragment<wmma::matrix_a, 16, 16, 16, __nv_bfloat16, wmma::row_major> fah[2], fal[2];
                wmma::fragment<wmma::matrix_b, 16, 16, 16, __nv_bfloat16, wmma::col_major> fbh[4], fbl[4];
                #pragma unroll
                for (int i = 0; i < 2; ++i) {
                    wmma::load_matrix_sync(fah[i], sAh + (wm * 32 + i * 16) * LDA2 + kk * 16, LDA2);
                    wmma::load_matrix_sync(fal[i], sAl + (wm * 32 + i * 16) * LDA2 + kk * 16, LDA2);
                }
                #pragma unroll
                for (int j = 0; j < 4; ++j) {
                    wmma::load_matrix_sync(fbh[j], sWh + (wn * 64 + j * 16) * LDW2 + c * 32 + kk * 16, LDW2);
                    wmma::load_matrix_sync(fbl[j], sWl + (wn * 64 + j * 16) * LDW2 + c * 32 + kk * 16, LDW2);
                }
                #pragma unroll
                for (int i = 0; i < 2; ++i)
                    #pragma unroll
                    for (int j = 0; j < 4; ++j) {
                        wmma::mma_sync(acc[i][j], fah[i], fbh[j], acc[i][j]);
                        wmma::mma_sync(acc[i][j], fah[i], fbl[j], acc[i][j]);
                        wmma::mma_sync(acc[i][j], fal[i], fbh[j], acc[i][j]);
                    }
            }
        }

        // ---- epilogue for this row-tile ----
        __syncthreads();   // sEpi free (prior write-out finished well before)
        #pragma unroll
        for (int i = 0; i < 2; ++i)
            #pragma unroll
            for (int j = 0; j < 4; ++j) {
                wmma::store_matrix_sync(sEpi + (wm * 32 + i * 16) * LDE2 + wn * 64 + j * 16,
                                        acc[i][j], LDE2, wmma::mem_row_major);
                wmma::fill_fragment(acc[i][j], 0.f);
            }
        __syncthreads();
        for (int idx = tid; idx < 128 * 32; idx += 256) {
            int r = idx >> 5, c4 = (idx & 31) * 4;
            float4 v = *(float4*)&sEpi[r * LDE2 + c4];
            v.x += sBias[c4 + 0]; v.y += sBias[c4 + 1];
            v.z += sBias[c4 + 2]; v.w += sBias[c4 + 3];
            *(float4*)(Cb + (m0 + r) * H3 + ncol0 + c4) = v;
        }
    }
}

// ---------------- tensor-core GRU layer (unchanged from R7) ----------------
#define LDWP 392
#define LDH  136
#define LDEPI 196
#define GOFF_WH  0
#define GOFF_WL  (GOFF_WH + 128 * LDWP * 2)
#define GOFF_HH  (GOFF_WL + 128 * LDWP * 2)
#define GOFF_HL  (GOFF_HH + TB * LDH * 2)
#define GOFF_EPI (GOFF_HL + TB * LDH * 2)
#define GOFF_BHH (GOFF_EPI + TB * LDEPI * 4)
#define GOFF_BIH (GOFF_BHH + H3 * 4)
#define GOFF_WIH (GOFF_BIH + H3 * 4)
#define SMEM_GRUTC (GOFF_WIH + H3 * 2 * 4)

template <int LAYER>
__global__ __launch_bounds__(512, 1) void gru_tc(
    const float* __restrict__ code,
    const float* __restrict__ xg,
    const float* __restrict__ Wih_f, const float* __restrict__ Wih_b,
    const float* __restrict__ Whh_f, const float* __restrict__ Whh_b,
    const float* __restrict__ bih_f, const float* __restrict__ bih_b,
    const float* __restrict__ bhh_f, const float* __restrict__ bhh_b,
    float* __restrict__ houtF,
    __nv_bfloat16* __restrict__ houtH,
    __nv_bfloat16* __restrict__ houtL)
{
    extern __shared__ char smem[];
    __nv_bfloat16* sWh = (__nv_bfloat16*)(smem + GOFF_WH);
    __nv_bfloat16* sWl = (__nv_bfloat16*)(smem + GOFF_WL);
    __nv_bfloat16* sHh = (__nv_bfloat16*)(smem + GOFF_HH);
    __nv_bfloat16* sHl = (__nv_bfloat16*)(smem + GOFF_HL);
    float* sEpi = (float*)(smem + GOFF_EPI);
    float* sBhh = (float*)(smem + GOFF_BHH);
    float* sBih = (float*)(smem + GOFF_BIH);
    float* sWih = (float*)(smem + GOFF_WIH);

    const int tid = threadIdx.x;
    const int dir = blockIdx.y;
    const int gb0 = blockIdx.x * TB;
    const float* Whh = dir ? Whh_b : Whh_f;
    const float* bhh = dir ? bhh_b : bhh_f;

    for (int idx = tid; idx < H3 * HID; idx += 512) {
        int r = idx >> 7, j = idx & 127;
        int g = r >> 7, k = r & 127;
        int colp = (k >> 6) * 192 + 3 * (k & 63) + g;
        float w = Whh[r * HID + j];
        __nv_bfloat16 hi = __float2bfloat16(w);
        __nv_bfloat16 lo = __float2bfloat16(w - __bfloat162float(hi));
        sWh[j * LDWP + colp] = hi;
        sWl[j * LDWP + colp] = lo;
    }
    for (int idx = tid; idx < H3; idx += 512) {
        sBhh[idx] = bhh[idx];
        if (LAYER == 0) {
            const float* Wih = dir ? Wih_b : Wih_f;
            const float* bih = dir ? bih_b : bih_f;
            sBih[idx] = bih[idx];
            sWih[idx * 2 + 0] = Wih[idx * 2 + 0];
            sWih[idx * 2 + 1] = Wih[idx * 2 + 1];
        }
    }
    for (int idx = tid; idx < TB * LDH; idx += 512) {
        sHh[idx] = __float2bfloat16(0.f);
        sHl[idx] = __float2bfloat16(0.f);
    }
    __syncthreads();

    const int wid = tid >> 5, lane = tid & 31;
    const int b = wid;
    const int k0 = lane * 2;
    float h[4] = {0.f, 0.f, 0.f, 0.f};

    for (int t = 0; t < SEQ; ++t) {
        const int tt = dir ? (SEQ - 1 - t) : t;

        float xr[4], xz[4], xn[4];
        if (LAYER == 1) {
            const float* xp = xg + ((size_t)dir * BL + (size_t)(gb0 + b) * SEQ + tt) * H3;
            float2 v;
            v = *(const float2*)(xp + k0);            xr[0] = v.x; xr[1] = v.y;
            v = *(const float2*)(xp + 64 + k0);       xr[2] = v.x; xr[3] = v.y;
            v = *(const float2*)(xp + 128 + k0);      xz[0] = v.x; xz[1] = v.y;
            v = *(const float2*)(xp + 192 + k0);      xz[2] = v.x; xz[3] = v.y;
            v = *(const float2*)(xp + 256 + k0);      xn[0] = v.x; xn[1] = v.y;
            v = *(const float2*)(xp + 320 + k0);      xn[2] = v.x; xn[3] = v.y;
        } else {
            float c0 = __ldg(&code[(size_t)(gb0 + b) * NLIN + tt * 2 + 0]);
            float c1 = __ldg(&code[(size_t)(gb0 + b) * NLIN + tt * 2 + 1]);
            #pragma unroll
            for (int i = 0; i < 4; ++i) {
                int k = (i >> 1) * 64 + k0 + (i & 1);
                xr[i] = fmaf(c0, sWih[k * 2],           fmaf(c1, sWih[k * 2 + 1],           sBih[k]));
                xz[i] = fmaf(c0, sWih[(128 + k) * 2],   fmaf(c1, sWih[(128 + k) * 2 + 1],   sBih[128 + k]));
                xn[i] = fmaf(c0, sWih[(256 + k) * 2],   fmaf(c1, sWih[(256 + k) * 2 + 1],   sBih[256 + k]));
            }
        }

        wmma::fragment<wmma::matrix_a, 16, 16, 16, __nv_bfloat16, wmma::row_major> aH[8], aL[8];
        if (wid < 12) {
            wmma::fragment<wmma::accumulator, 16, 16, 16, float> acc;
            wmma::fill_fragment(acc, 0.f);
            #pragma unroll
            for (int jf = 0; jf < 8; ++jf) {
                wmma::fragment<wmma::matrix_b, 16, 16, 16, __nv_bfloat16, wmma::row_major> bH, bL;
                wmma::load_matrix_sync(aH[jf], sHh + jf * 16, LDH);
                wmma::load_matrix_sync(aL[jf], sHl + jf * 16, LDH);
                wmma::load_matrix_sync(bH, sWh + (jf * 16) * LDWP + wid * 16, LDWP);
                wmma::load_matrix_sync(bL, sWl + (jf * 16) * LDWP + wid * 16, LDWP);
                wmma::mma_sync(acc, aH[jf], bH, acc);
                wmma::mma_sync(acc, aH[jf], bL, acc);
                wmma::mma_sync(acc, aL[jf], bH, acc);
            }
            wmma::store_matrix_sync(sEpi + wid * 16, acc, LDEPI, wmma::mem_row_major);
        }
        __syncthreads();

        #pragma unroll
        for (int i = 0; i < 2; ++i) {
            int k = k0 + i;
            const float* e = sEpi + b * LDEPI + 3 * k;
            float r = sigf(xr[i] + e[0] + sBhh[k]);
            float z = sigf(xz[i] + e[1] + sBhh[128 + k]);
            float n = tanhfast(xn[i] + r * (e[2] + sBhh[256 + k]));
            h[i] = (1.f - z) * n + z * h[i];
        }
        __syncthreads();

        if (wid < 12) {
            wmma::fragment<wmma::accumulator, 16, 16, 16, float> acc;
            wmma::fill_fragment(acc, 0.f);
            #pragma unroll
            for (int jf = 0; jf < 8; ++jf) {
                wmma::fragment<wmma::matrix_b, 16, 16, 16, __nv_bfloat16, wmma::row_major> bH, bL;
                wmma::load_matrix_sync(bH, sWh + (jf * 16) * LDWP + 192 + wid * 16, LDWP);
                wmma::load_matrix_sync(bL, sWl + (jf * 16) * LDWP + 192 + wid * 16, LDWP);
                wmma::mma_sync(acc, aH[jf], bH, acc);
                wmma::mma_sync(acc, aH[jf], bL, acc);
                wmma::mma_sync(acc, aL[jf], bH, acc);
            }
            wmma::store_matrix_sync(sEpi + wid * 16, acc, LDEPI, wmma::mem_row_major);
        }
        __syncthreads();

        #pragma unroll
        for (int i = 0; i < 2; ++i) {
            int kk = k0 + i;
            int k = 64 + kk;
            const float* e = sEpi + b * LDEPI + 3 * kk;
            float r = sigf(xr[2 + i] + e[0] + sBhh[k]);
            float z = sigf(xz[2 + i] + e[1] + sBhh[128 + k]);
            float n = tanhfast(xn[2 + i] + r * (e[2] + sBhh[256 + k]));
            h[2 + i] = (1.f - z) * n + z * h[2 + i];
        }

        const size_t orow = ((size_t)(gb0 + b) * SEQ + tt) * H2 + dir * HID;
        #pragma unroll
        for (int i = 0; i < 4; ++i) {
            int k = (i >> 1) * 64 + k0 + (i & 1);
            float v = h[i];
            __nv_bfloat16 hi = __float2bfloat16(v);
            __nv_bfloat16 lo = __float2bfloat16(v - __bfloat162float(hi));
            sHh[b * LDH + k] = hi;
            sHl[b * LDH + k] = lo;
            if (LAYER == 0) {
                houtH[orow + k] = hi;
                houtL[orow + k] = lo;
            } else {
                houtF[orow + k] = v;
            }
        }
        __syncthreads();
    }
}

// ---------------- final head ----------------
__global__ __launch_bounds__(256) void final_kernel(
    const float* __restrict__ h1, const float* __restrict__ Wf,
    const float* __restrict__ bf, float* __restrict__ out)
{
    __shared__ float sW[H2];
    int tid = threadIdx.x;
    sW[tid] = Wf[tid];
    __syncthreads();
    int w = tid >> 5, l = tid & 31;
    size_t row = (size_t)blockIdx.x * 8 + w;
    const float* hr = h1 + row * H2;
    float s = 0.f;
    #pragma unroll
    for (int i = 0; i < 8; ++i)
        s = fmaf(hr[l + i * 32], sW[l + i * 32], s);
    #pragma unroll
    for (int off = 16; off; off >>= 1)
        s += __shfl_xor_sync(0xffffffffu, s, off);
    if (l == 0)
        out[row] = 1.f / (1.f + __expf(-(s + bf[0])));
}

// ---------------- launch ----------------
extern "C" void kernel_launch(void* const* d_in, const int* in_sizes, int n_in,
                              void* d_out, int out_size)
{
    const float* received = (const float*)d_in[0];
    const float* W_lin    = (const float*)d_in[1];
    const float* b_lin    = (const float*)d_in[2];
    const float* Wih0f = (const float*)d_in[3],  *Whh0f = (const float*)d_in[4];
    const float* bih0f = (const float*)d_in[5],  *bhh0f = (const float*)d_in[6];
    const float* Wih0b = (const float*)d_in[7],  *Whh0b = (const float*)d_in[8];
    const float* bih0b = (const float*)d_in[9],  *bhh0b = (const float*)d_in[10];
    const float* Wih1f = (const float*)d_in[11], *Whh1f = (const float*)d_in[12];
    const float* bih1f = (const float*)d_in[13], *bhh1f = (const float*)d_in[14];
    const float* Wih1b = (const float*)d_in[15], *Whh1b = (const float*)d_in[16];
    const float* bih1b = (const float*)d_in[17], *bhh1b = (const float*)d_in[18];
    const float* Wf    = (const float*)d_in[19], *bf    = (const float*)d_in[20];
    float* out = (float*)d_out;

    float *code, *xg1, *h1;
    __nv_bfloat16 *ah, *al;
    cudaGetSymbolAddress((void**)&code, g_code);
    cudaGetSymbolAddress((void**)&ah,   g_ah);
    cudaGetSymbolAddress((void**)&al,   g_al);
    cudaGetSymbolAddress((void**)&xg1,  g_xg1);
    cudaGetSymbolAddress((void**)&h1,   g_h1);

    cudaFuncSetAttribute(gru_tc<0>, cudaFuncAttributeMaxDynamicSharedMemorySize, (int)SMEM_GRUTC);
    cudaFuncSetAttribute(gru_tc<1>, cudaFuncAttributeMaxDynamicSharedMemorySize, (int)SMEM_GRUTC);
    cudaFuncSetAttribute(xgemm2, cudaFuncAttributeMaxDynamicSharedMemorySize, (int)SMEM_X2);

    // 1) dec_linear
    sgemm_nt<<<dim3(BATCH / 64, (NLIN + 63) / 64), 256>>>(
        received, W_lin, b_lin, code, BATCH, NLIN, NLIN);

    // 2) layer-0 bidirectional GRU (tensor-core recurrence) -> bf16 hi/lo h0
    gru_tc<0><<<dim3(BATCH / TB, 2), 512, SMEM_GRUTC>>>(
        code, nullptr, Wih0f, Wih0b, Whh0f, Whh0b, bih0f, bih0b, bhh0f, bhh0b,
        nullptr, ah, al);

    // 3) layer-1 input projections (wmma bf16 v2)
    xgemm2<<<dim3(6, 200), 256, SMEM_X2>>>(
        ah, al, Wih1f, Wih1b, bih1f, bih1b, xg1);

    // 4) layer-1 bidirectional GRU (tensor-core recurrence)
    gru_tc<1><<<dim3(BATCH / TB, 2), 512, SMEM_GRUTC>>>(
        nullptr, xg1, nullptr, nullptr, Whh1f, Whh1b, bih1f, bih1b, bhh1f, bhh1b,
        h1, nullptr, nullptr);

    // 5) output head
    final_kernel<<<BL / 8, 256>>>(h1, Wf, bf, out);
}